// round 15
// baseline (speedup 1.0000x reference)
#include <cuda_runtime.h>
#include <cuda_bf16.h>
#include <cstdint>

typedef __nv_bfloat16 bf16;

// Output layout (floats): out, z_all, key_rope_all, attn_weights, scores
#define OUT_OUT    0L
#define OUT_ZALL   4194304L
#define OUT_KRA    8388608L
#define OUT_ATTN   12582912L
#define OUT_SCORES 79691776L

// ---------------------------------------------------------------------------
// Scratch
// ---------------------------------------------------------------------------
__device__ float g_qx    [2048L*1024];
__device__ float g_kx    [2048L*1024];

__device__ bf16 g_xh[2048L*2048], g_xl[2048L*2048];
__device__ bf16 g_zallh[4096L*1024], g_zalll[4096L*1024];
__device__ bf16 g_qlath[2048L*1024], g_qlatl[2048L*1024];
__device__ bf16 g_qh [2048L*1024], g_ql [2048L*1024];
__device__ bf16 g_qrh[2048L*1024], g_qrl[2048L*1024];
__device__ bf16 g_kch[4096L*1024], g_kcl[4096L*1024];
__device__ bf16 g_krah[4096L*1024], g_kral[4096L*1024];
__device__ bf16 g_vth[2L*1024*2048], g_vtl[2L*1024*2048];
__device__ bf16 g_hoh[2048L*1024], g_hol[2048L*1024];
__device__ bf16 g_pbh[67108864L], g_pbl[67108864L];

__device__ bf16 g_WlatTh[2097152], g_WlatTl[2097152];
__device__ bf16 g_WqdTh [2097152], g_WqdTl [2097152];
__device__ bf16 g_WquTh [1048576], g_WquTl [1048576];
__device__ bf16 g_WxrTh [1048576], g_WxrTl [1048576];
__device__ bf16 g_WkuTh [1048576], g_WkuTl [1048576];
__device__ bf16 g_WvuTh [1048576], g_WvuTl [1048576];
__device__ bf16 g_WkrTh [2097152], g_WkrTl [2097152];
__device__ bf16 g_WoTh  [2097152], g_WoTl  [2097152];

// ---------------------------------------------------------------------------
// Helpers
// ---------------------------------------------------------------------------
__device__ __forceinline__ uint32_t smem_u32(const void* p) {
    uint32_t a;
    asm("{ .reg .u64 t; cvta.to.shared.u64 t, %1; cvt.u32.u64 %0, t; }" : "=r"(a) : "l"(p));
    return a;
}
#define SW128X(o) ((o) ^ (((o) >> 3) & 0x70))

__device__ __forceinline__ void ldm4(uint32_t* r, uint32_t addr) {
    asm volatile("ldmatrix.sync.aligned.m8n8.x4.shared.b16 {%0,%1,%2,%3}, [%4];"
        : "=r"(r[0]), "=r"(r[1]), "=r"(r[2]), "=r"(r[3]) : "r"(addr));
}
__device__ __forceinline__ void mma_bf16(float* c, const uint32_t* a, const uint32_t* b) {
    asm volatile("mma.sync.aligned.m16n8k16.row.col.f32.bf16.bf16.f32 "
        "{%0,%1,%2,%3}, {%4,%5,%6,%7}, {%8,%9}, {%0,%1,%2,%3};"
        : "+f"(c[0]), "+f"(c[1]), "+f"(c[2]), "+f"(c[3])
        : "r"(a[0]), "r"(a[1]), "r"(a[2]), "r"(a[3]), "r"(b[0]), "r"(b[1]));
}
__device__ __forceinline__ void cp16(uint32_t dst, const void* src) {
    asm volatile("cp.async.cg.shared.global [%0], [%1], 16;" :: "r"(dst), "l"(src));
}
__device__ __forceinline__ uint32_t pack2(float a, float b) {
    bf16 ha = __float2bfloat16(a), hb = __float2bfloat16(b);
    return (uint32_t)((__nv_bfloat16_raw)ha).x | ((uint32_t)((__nv_bfloat16_raw)hb).x << 16);
}

// ---------------------------------------------------------------------------
// Split-bf16 HMMA GEMM; accum flag adds into existing C.
// ---------------------------------------------------------------------------
template<int NT>
__global__ void __launch_bounds__(256, NT == 64 ? 2 : 1) gemm_tc(
    const bf16* __restrict__ Ah, const bf16* __restrict__ Al,
    const bf16* __restrict__ Bh, const bf16* __restrict__ Bl,
    float* C, const float* bias, bf16* Ch, bf16* Cl,
    int K, int lda, int ldb, int ldc,
    int HD, long sA1, long sA2, long sB1, long sB2, long sC1, long sC2,
    float alpha, int accum)
{
    constexpr int MI   = (NT == 128) ? 4 : 2;
    constexpr int NB   = NT / 32;
    constexpr int ABY  = 128 * 128;
    constexpr int BBY  = NT * 128;
    constexpr int BUFB = 2 * ABY + 2 * BBY;

    extern __shared__ char smem[];
    uint32_t base = (smem_u32(smem) + 1023u) & ~1023u;

    int tid = threadIdx.x;
    int lane = tid & 31, wid = tid >> 5;

    int wm = (NT == 128) ? (wid & 1) * 64 : (wid & 3) * 32;
    int wn = (NT == 128) ? (wid >> 1) * 32 : (wid >> 2) * 32;

    int z = blockIdx.z;
    int z1 = z / HD, z2 = z - z1 * HD;
    long aoff = (long)z1*sA1 + (long)z2*sA2 + (long)blockIdx.y*128*lda;
    long boff = (long)z1*sB1 + (long)z2*sB2 + (long)blockIdx.x*NT*ldb;
    const bf16 *Abh = Ah + aoff, *Abl = Al + aoff;
    const bf16 *Bbh = Bh + boff, *Bbl = Bl + boff;

    int a_r = (lane & 7) + (((lane >> 3) & 1) << 3);
    int a_c = (lane >> 4) & 1;
    int b_r = (lane & 7) + ((lane & 16) ? 8 : 0);
    int b_c = (lane >> 3) & 1;

    float acc[MI][4][4];
    #pragma unroll
    for (int i = 0; i < MI; i++)
        #pragma unroll
        for (int j = 0; j < 4; j++)
            #pragma unroll
            for (int q = 0; q < 4; q++) acc[i][j][q] = 0.f;

    int lr = tid >> 3, lc = tid & 7;
    int nch = K >> 6;

    auto load_chunk = [&](int kk, int buf) {
        uint32_t aH = base + (uint32_t)buf * BUFB;
        uint32_t aL = aH + ABY, bH = aL + ABY, bL = bH + BBY;
        #pragma unroll
        for (int it = 0; it < 4; it++) {
            int r = lr + it * 32;
            uint32_t off = SW128X((uint32_t)(r * 128 + lc * 16));
            cp16(aH + off, Abh + (long)r * lda + kk + lc * 8);
            cp16(aL + off, Abl + (long)r * lda + kk + lc * 8);
        }
        #pragma unroll
        for (int it = 0; it < NB; it++) {
            int r = lr + it * 32;
            uint32_t off = SW128X((uint32_t)(r * 128 + lc * 16));
            cp16(bH + off, Bbh + (long)r * ldb + kk + lc * 8);
            cp16(bL + off, Bbl + (long)r * ldb + kk + lc * 8);
        }
        asm volatile("cp.async.commit_group;");
    };

    load_chunk(0, 0);

    for (int c = 0; c < nch; c++) {
        if (c + 1 < nch) {
            load_chunk((c + 1) << 6, (c + 1) & 1);
            asm volatile("cp.async.wait_group 1;");
        } else {
            asm volatile("cp.async.wait_group 0;");
        }
        __syncthreads();

        uint32_t aH = base + (uint32_t)(c & 1) * BUFB;
        uint32_t aL = aH + ABY, bH = aL + ABY, bL = bH + BBY;

        #pragma unroll
        for (int ks = 0; ks < 4; ks++) {
            uint32_t afh[MI][4], afl[MI][4], bfh[8], bfl[8];
            #pragma unroll
            for (int mi = 0; mi < MI; mi++) {
                int row = wm + mi * 16 + a_r;
                uint32_t off = (uint32_t)(row * 128) + ((((ks << 1) + a_c) ^ (row & 7)) << 4);
                ldm4(afh[mi], aH + off);
                ldm4(afl[mi], aL + off);
            }
            #pragma unroll
            for (int np = 0; np < 2; np++) {
                int row = wn + np * 16 + b_r;
                uint32_t off = (uint32_t)(row * 128) + ((((ks << 1) + b_c) ^ (row & 7)) << 4);
                ldm4(&bfh[np * 4], bH + off);
                ldm4(&bfl[np * 4], bL + off);
            }
            #pragma unroll
            for (int mi = 0; mi < MI; mi++)
                #pragma unroll
                for (int ni = 0; ni < 4; ni++)
                    mma_bf16(acc[mi][ni], afh[mi], &bfh[ni * 2]);
            #pragma unroll
            for (int mi = 0; mi < MI; mi++)
                #pragma unroll
                for (int ni = 0; ni < 4; ni++)
                    mma_bf16(acc[mi][ni], afl[mi], &bfh[ni * 2]);
            #pragma unroll
            for (int mi = 0; mi < MI; mi++)
                #pragma unroll
                for (int ni = 0; ni < 4; ni++)
                    mma_bf16(acc[mi][ni], afh[mi], &bfl[ni * 2]);
        }
        __syncthreads();
    }

    long coff = (long)z1*sC1 + (long)z2*sC2
              + (long)blockIdx.y*128*ldc + (long)blockIdx.x*NT;
    int colg0 = blockIdx.x * NT;
    #pragma unroll
    for (int mi = 0; mi < MI; mi++) {
        #pragma unroll
        for (int ni = 0; ni < 4; ni++) {
            int col = wn + ni*8 + (lane & 3)*2;
            float bv0 = 0.f, bv1 = 0.f;
            if (bias) { bv0 = bias[colg0 + col]; bv1 = bias[colg0 + col + 1]; }
            int r0 = wm + mi*16 + (lane >> 2);
            float v00 = acc[mi][ni][0]*alpha + bv0, v01 = acc[mi][ni][1]*alpha + bv1;
            float v10 = acc[mi][ni][2]*alpha + bv0, v11 = acc[mi][ni][3]*alpha + bv1;
            if (C) {
                float* c0 = C + coff + (long)r0*ldc + col;
                float* c1 = C + coff + (long)(r0+8)*ldc + col;
                if (accum) {
                    float2 o0 = *(float2*)c0, o1 = *(float2*)c1;
                    v00 += o0.x; v01 += o0.y;
                    v10 += o1.x; v11 += o1.y;
                }
                *(float2*)c0 = make_float2(v00, v01);
                *(float2*)c1 = make_float2(v10, v11);
            }
            if (Ch) {
                bf16 h00 = __float2bfloat16(v00), h01 = __float2bfloat16(v01);
                bf16 h10 = __float2bfloat16(v10), h11 = __float2bfloat16(v11);
                *(__nv_bfloat162*)(Ch + coff + (long)r0*ldc + col) = __nv_bfloat162(h00, h01);
                *(__nv_bfloat162*)(Ch + coff + (long)(r0+8)*ldc + col) = __nv_bfloat162(h10, h11);
                bf16 l00 = __float2bfloat16(v00 - __bfloat162float(h00));
                bf16 l01 = __float2bfloat16(v01 - __bfloat162float(h01));
                bf16 l10 = __float2bfloat16(v10 - __bfloat162float(h10));
                bf16 l11 = __float2bfloat16(v11 - __bfloat162float(h11));
                *(__nv_bfloat162*)(Cl + coff + (long)r0*ldc + col) = __nv_bfloat162(l00, l01);
                *(__nv_bfloat162*)(Cl + coff + (long)(r0+8)*ldc + col) = __nv_bfloat162(l10, l11);
            }
        }
    }
}

// ---------------------------------------------------------------------------
// Elementwise helpers (unchanged)
// ---------------------------------------------------------------------------
__global__ void split_kernel(const float* __restrict__ in, bf16* __restrict__ oh,
                             bf16* __restrict__ ol, long n)
{
    long i = ((long)blockIdx.x * 256 + threadIdx.x) * 4;
    if (i >= n) return;
    float4 v = *(const float4*)(in + i);
    float a[4] = {v.x, v.y, v.z, v.w};
    bf16 h0 = __float2bfloat16(a[0]), h1 = __float2bfloat16(a[1]);
    bf16 h2 = __float2bfloat16(a[2]), h3 = __float2bfloat16(a[3]);
    uint2 ho, lo;
    ho.x = pack2(a[0], a[1]); ho.y = pack2(a[2], a[3]);
    lo.x = pack2(a[0] - __bfloat162float(h0), a[1] - __bfloat162float(h1));
    lo.y = pack2(a[2] - __bfloat162float(h2), a[3] - __bfloat162float(h3));
    *(uint2*)(oh + i) = ho;
    *(uint2*)(ol + i) = lo;
}

__global__ void transpose_split(const float* __restrict__ in, bf16* __restrict__ oh,
                                bf16* __restrict__ ol, int R, int C, long sIn, long sOut)
{
    __shared__ float t[32][33];
    long ib = (long)blockIdx.z * sIn, ob = (long)blockIdx.z * sOut;
    int x = blockIdx.x * 32 + threadIdx.x;
    int y0 = blockIdx.y * 32;
    #pragma unroll
    for (int j = threadIdx.y; j < 32; j += 8)
        t[j][threadIdx.x] = in[ib + (long)(y0 + j) * C + x];
    __syncthreads();
    int ox = blockIdx.y * 32 + threadIdx.x;
    int oy0 = blockIdx.x * 32;
    #pragma unroll
    for (int j = threadIdx.y; j < 32; j += 8) {
        float v = t[threadIdx.x][j];
        bf16 h = __float2bfloat16(v);
        long o = ob + (long)(oy0 + j) * R + ox;
        oh[o] = h;
        ol[o] = __float2bfloat16(v - __bfloat162float(h));
    }
}

__global__ void copy_concat_split(const float* __restrict__ src, float* __restrict__ dst,
                                  bf16* __restrict__ oh, bf16* __restrict__ ol)
{
    long u = (long)blockIdx.x * 256 + threadIdx.x;
    if (u >= 524288L) return;
    long i = u * 4;
    long r = i >> 10, c = i & 1023;
    long b = r >> 10, l = r & 1023;
    long o = ((b * 2048) + l) * 1024 + c;
    float4 v = *(const float4*)(src + i);
    *(float4*)(dst + o) = v;
    float a[4] = {v.x, v.y, v.z, v.w};
    bf16 h0 = __float2bfloat16(a[0]), h1 = __float2bfloat16(a[1]);
    bf16 h2 = __float2bfloat16(a[2]), h3 = __float2bfloat16(a[3]);
    uint2 ho, lo;
    ho.x = pack2(a[0], a[1]); ho.y = pack2(a[2], a[3]);
    lo.x = pack2(a[0] - __bfloat162float(h0), a[1] - __bfloat162float(h1));
    lo.y = pack2(a[2] - __bfloat162float(h2), a[3] - __bfloat162float(h3));
    *(uint2*)(oh + o) = ho;
    *(uint2*)(ol + o) = lo;
}

__global__ void rotary_kernel(const float* __restrict__ src,
                              float* __restrict__ fdst,
                              bf16* __restrict__ oh, bf16* __restrict__ ol, int mode)
{
    int idx = blockIdx.x * 256 + threadIdx.x;
    if (idx >= 2048 * 16 * 32) return;
    int i = idx & 31;
    int h = (idx >> 5) & 15;
    int r = idx >> 9;
    int pos = r & 1023;
    float fr = __expf(-9.2103403719761836f * (float)i / 32.0f);
    float ang = (float)pos * fr;
    float sn, cs;
    sincosf(ang, &sn, &cs);
    const float* s = src + (long)r * 1024 + h * 64 + i;
    float s1 = s[0], s2 = s[32];
    float o1 = s1 * cs - s2 * sn;
    float o2 = s1 * sn + s2 * cs;
    long drow = mode ? ((long)(r >> 10) * 2048 + 1024 + (r & 1023)) : (long)r;
    long off = drow * 1024 + h * 64 + i;
    if (fdst) { fdst[off] = o1; fdst[off + 32] = o2; }
    bf16 h1 = __float2bfloat16(o1), h2 = __float2bfloat16(o2);
    oh[off]      = h1;
    oh[off + 32] = h2;
    ol[off]      = __float2bfloat16(o1 - __bfloat162float(h1));
    ol[off + 32] = __float2bfloat16(o2 - __bfloat162float(h2));
}

// Dual softmax, single-exp, vectorized; head-half variant.
__global__ void __launch_bounds__(256) softmax_kernel(
    const float* __restrict__ scores, const int* __restrict__ vlens,
    float* __restrict__ attn, bf16* __restrict__ ph_out, bf16* __restrict__ pl_out,
    int hOff)
{
    int b = blockIdx.y;
    long row = (long)b * 16384 + hOff * 1024 + blockIdx.x;
    int l = blockIdx.x & 1023;
    int vl = vlens[b * 1024 + l];
    const float* s = scores + row * 2048;
    int tid = threadIdx.x;
    int k0 = tid * 8;

    float4 v0 = *(const float4*)(s + k0);
    float4 v1 = *(const float4*)(s + k0 + 4);
    float va[8] = {v0.x, v0.y, v0.z, v0.w, v1.x, v1.y, v1.z, v1.w};

    float mu = -1e30f;
    #pragma unroll
    for (int i = 0; i < 8; i++) mu = fmaxf(mu, va[i]);
    __shared__ float red[16];
    #pragma unroll
    for (int o = 16; o > 0; o >>= 1)
        mu = fmaxf(mu, __shfl_xor_sync(0xffffffffu, mu, o));
    int w = tid >> 5, lane = tid & 31;
    if (lane == 0) red[w] = mu;
    __syncthreads();
    mu = -1e30f;
    #pragma unroll
    for (int i = 0; i < 8; i++) mu = fmaxf(mu, red[i]);
    __syncthreads();

    float su = 0.f, sm = 0.f;
    #pragma unroll
    for (int i = 0; i < 8; i++) {
        float e = __expf(va[i] - mu);
        va[i] = e;
        su += e;
        if (k0 + i < vl) sm += e;
    }
    #pragma unroll
    for (int o = 16; o > 0; o >>= 1) {
        su += __shfl_xor_sync(0xffffffffu, su, o);
        sm += __shfl_xor_sync(0xffffffffu, sm, o);
    }
    if (lane == 0) { red[w] = su; red[w + 8] = sm; }
    __syncthreads();
    su = 0.f; sm = 0.f;
    #pragma unroll
    for (int i = 0; i < 8; i++) { su += red[i]; sm += red[8 + i]; }
    float iu = 1.f / su, im = 1.f / sm;

    float* arow = attn + row * 2048;
    float4 a0, a1;
    a0.x = va[0]*iu; a0.y = va[1]*iu; a0.z = va[2]*iu; a0.w = va[3]*iu;
    a1.x = va[4]*iu; a1.y = va[5]*iu; a1.z = va[6]*iu; a1.w = va[7]*iu;
    *(float4*)(arow + k0)     = a0;
    *(float4*)(arow + k0 + 4) = a1;

    float p[8];
    #pragma unroll
    for (int i = 0; i < 8; i++) p[i] = (k0 + i < vl) ? va[i] * im : 0.f;
    uint4 ho, lo;
    bf16 hb[8];
    #pragma unroll
    for (int i = 0; i < 8; i++) hb[i] = __float2bfloat16(p[i]);
    ho.x = pack2(p[0], p[1]); ho.y = pack2(p[2], p[3]);
    ho.z = pack2(p[4], p[5]); ho.w = pack2(p[6], p[7]);
    lo.x = pack2(p[0] - __bfloat162float(hb[0]), p[1] - __bfloat162float(hb[1]));
    lo.y = pack2(p[2] - __bfloat162float(hb[2]), p[3] - __bfloat162float(hb[3]));
    lo.z = pack2(p[4] - __bfloat162float(hb[4]), p[5] - __bfloat162float(hb[5]));
    lo.w = pack2(p[6] - __bfloat162float(hb[6]), p[7] - __bfloat162float(hb[7]));
    *(uint4*)(ph_out + row * 2048 + k0) = ho;
    *(uint4*)(pl_out + row * 2048 + k0) = lo;
}

// ---------------------------------------------------------------------------
// Host launch — dual chains + split AV tail + K-split output GEMM
// ---------------------------------------------------------------------------
#define GSYM(p, s) cudaGetSymbolAddress((void**)&(p), s)

extern "C" void kernel_launch(void* const* d_in, const int* in_sizes, int n_in,
                              void* d_out, int out_size)
{
    const float* x        = (const float*)d_in[0];
    const float* z        = (const float*)d_in[1];
    const float* key_rope = (const float*)d_in[2];
    const int*   vlens    = (const int*)  d_in[3];
    const float* W_latent = (const float*)d_in[4];
    const float* W_q_down = (const float*)d_in[5];
    const float* b_q_down = (const float*)d_in[6];
    const float* W_q_up   = (const float*)d_in[7];
    const float* W_k_up   = (const float*)d_in[8];
    const float* W_v_up   = (const float*)d_in[9];
    const float* W_x_rope = (const float*)d_in[10];
    const float* W_k_rope = (const float*)d_in[11];
    const float* W_o      = (const float*)d_in[12];
    float* out = (float*)d_out;

    float *p_qx, *p_kx;
    bf16 *xh, *xl, *zh, *zl, *qlh, *qll, *qh, *ql, *qrh, *qrl,
         *kch, *kcl, *krah, *kral, *vth, *vtl, *hoh, *hol, *pbh, *pbl;
    bf16 *WlatTh, *WlatTl, *WqdTh, *WqdTl, *WquTh, *WquTl, *WxrTh, *WxrTl,
         *WkuTh, *WkuTl, *WvuTh, *WvuTl, *WkrTh, *WkrTl, *WoTh, *WoTl;

    GSYM(p_qx, g_qx); GSYM(p_kx, g_kx);
    GSYM(xh, g_xh); GSYM(xl, g_xl); GSYM(zh, g_zallh); GSYM(zl, g_zalll);
    GSYM(qlh, g_qlath); GSYM(qll, g_qlatl);
    GSYM(qh, g_qh); GSYM(ql, g_ql); GSYM(qrh, g_qrh); GSYM(qrl, g_qrl);
    GSYM(kch, g_kch); GSYM(kcl, g_kcl); GSYM(krah, g_krah); GSYM(kral, g_kral);
    GSYM(vth, g_vth); GSYM(vtl, g_vtl); GSYM(hoh, g_hoh); GSYM(hol, g_hol);
    GSYM(pbh, g_pbh); GSYM(pbl, g_pbl);
    GSYM(WlatTh, g_WlatTh); GSYM(WlatTl, g_WlatTl);
    GSYM(WqdTh, g_WqdTh);   GSYM(WqdTl, g_WqdTl);
    GSYM(WquTh, g_WquTh);   GSYM(WquTl, g_WquTl);
    GSYM(WxrTh, g_WxrTh);   GSYM(WxrTl, g_WxrTl);
    GSYM(WkuTh, g_WkuTh);   GSYM(WkuTl, g_WkuTl);
    GSYM(WvuTh, g_WvuTh);   GSYM(WvuTl, g_WvuTl);
    GSYM(WkrTh, g_WkrTh);   GSYM(WkrTl, g_WkrTl);
    GSYM(WoTh, g_WoTh);     GSYM(WoTl, g_WoTl);

    const int SMB64  = 99328;
    const int SMB128 = 132096;
    cudaFuncSetAttribute(gemm_tc<64>,  cudaFuncAttributeMaxDynamicSharedMemorySize, SMB64);
    cudaFuncSetAttribute(gemm_tc<128>, cudaFuncAttributeMaxDynamicSharedMemorySize, SMB128);
    dim3 tb(32, 8);

    static cudaStream_t s1 = nullptr;
    static cudaEvent_t eStart = nullptr, eX = nullptr, eKeyc = nullptr,
                       eRotQ = nullptr, eS1 = nullptr, eVal = nullptr,
                       eSm0 = nullptr, eOut1 = nullptr;
    if (!s1) {
        cudaStreamCreateWithFlags(&s1, cudaStreamNonBlocking);
        cudaEventCreateWithFlags(&eStart, cudaEventDisableTiming);
        cudaEventCreateWithFlags(&eX,     cudaEventDisableTiming);
        cudaEventCreateWithFlags(&eKeyc,  cudaEventDisableTiming);
        cudaEventCreateWithFlags(&eRotQ,  cudaEventDisableTiming);
        cudaEventCreateWithFlags(&eS1,    cudaEventDisableTiming);
        cudaEventCreateWithFlags(&eVal,   cudaEventDisableTiming);
        cudaEventCreateWithFlags(&eSm0,   cudaEventDisableTiming);
        cudaEventCreateWithFlags(&eOut1,  cudaEventDisableTiming);
    }

    // === fork at t=0 ===
    cudaEventRecord(eStart, 0);
    cudaStreamWaitEvent(s1, eStart, 0);

    // === chain B (s1): transposes + z copy (overlap x split), then z path ===
    transpose_split<<<dim3(32, 64, 1), tb, 0, s1>>>(W_latent, WlatTh, WlatTl, 2048, 1024, 0, 0);
    transpose_split<<<dim3(32, 32, 1), tb, 0, s1>>>(W_k_up,   WkuTh,  WkuTl,  1024, 1024, 0, 0);
    transpose_split<<<dim3(32, 32, 1), tb, 0, s1>>>(W_v_up,   WvuTh,  WvuTl,  1024, 1024, 0, 0);
    transpose_split<<<dim3(32, 64, 1), tb, 0, s1>>>(W_k_rope, WkrTh,  WkrTl,  2048, 1024, 0, 0);
    copy_concat_split<<<2048, 256, 0, s1>>>(z, out + OUT_ZALL, zh, zl);

    // === chain A (main): x split + q-path weights ===
    split_kernel<<<4096, 256>>>(x, xh, xl, 4194304L);
    cudaEventRecord(eX, 0);
    transpose_split<<<dim3(32, 64, 1), tb>>>(W_q_down, WqdTh, WqdTl, 2048, 1024, 0, 0);
    transpose_split<<<dim3(32, 32, 1), tb>>>(W_q_up,   WquTh, WquTl, 1024, 1024, 0, 0);
    transpose_split<<<dim3(32, 32, 1), tb>>>(W_x_rope, WxrTh, WxrTl, 1024, 1024, 0, 0);
    transpose_split<<<dim3(64, 32, 1), tb>>>(W_o,      WoTh,  WoTl,  1024, 2048, 0, 0);
    copy_concat_split<<<2048, 256>>>(key_rope, out + OUT_KRA, krah, kral);

    // === chain B GEMMs: z_all -> key_c -> vt -> kx -> rotary-k ===
    cudaStreamWaitEvent(s1, eX, 0);
    gemm_tc<64><<<dim3(16, 8, 2), 256, SMB64, s1>>>(
        xh, xl, WlatTh, WlatTl, out + OUT_ZALL + 1024L * 1024, nullptr,
        zh + 1024L * 1024, zl + 1024L * 1024,
        2048, 2048, 2048, 1024,
        1, 1024L * 2048, 0, 0, 0, 2048L * 1024, 0, 1.f, 0);
    gemm_tc<64><<<dim3(16, 32, 1), 256, SMB64, s1>>>(
        zh, zl, WkuTh, WkuTl, nullptr, nullptr, kch, kcl,
        1024, 1024, 1024, 1024, 1, 0, 0, 0, 0, 0, 0, 1.f, 0);
    cudaEventRecord(eKeyc, s1);
    // vt[b] = W_v_up^T(split) @ z_all[b]^T
    gemm_tc<64><<<dim3(32, 8, 2), 256, SMB64, s1>>>(
        WvuTh, WvuTl, zh, zl, nullptr, nullptr, vth, vtl,
        1024, 1024, 1024, 2048,
        1, 0, 0, 2048L * 1024, 0, 1024L * 2048, 0, 1.f, 0);
    cudaEventRecord(eVal, s1);
    // kx = x @ W_k_rope
    gemm_tc<64><<<dim3(16, 16, 1), 256, SMB64, s1>>>(
        xh, xl, WkrTh, WkrTl, p_kx, nullptr, nullptr, nullptr,
        2048, 2048, 2048, 1024, 1, 0, 0, 0, 0, 0, 0, 1.f, 0);
    rotary_kernel<<<4096, 256, 0, s1>>>(p_kx, out + OUT_KRA, krah, kral, 1);

    // === chain A GEMMs: q_lat -> qx -> query -> rotary-q ===
    gemm_tc<64><<<dim3(16, 16, 1), 256, SMB64>>>(
        xh, xl, WqdTh, WqdTl, nullptr, b_q_down, qlh, qll,
        2048, 2048, 2048, 1024, 1, 0, 0, 0, 0, 0, 0, 1.f, 0);
    gemm_tc<64><<<dim3(16, 16, 1), 256, SMB64>>>(
        qlh, qll, WxrTh, WxrTl, p_qx, nullptr, nullptr, nullptr,
        1024, 1024, 1024, 1024, 1, 0, 0, 0, 0, 0, 0, 1.f, 0);
    gemm_tc<64><<<dim3(16, 16, 1), 256, SMB64>>>(
        qlh, qll, WquTh, WquTl, nullptr, nullptr, qh, ql,
        1024, 1024, 1024, 1024, 1, 0, 0, 0, 0, 0, 0, 1.f, 0);
    rotary_kernel<<<4096, 256>>>(p_qx, nullptr, qrh, qrl, 0);
    cudaEventRecord(eRotQ, 0);

    // === s1: scores h8-15 (needs rotary-q from main + rotary-k local) ===
    cudaStreamWaitEvent(s1, eRotQ, 0);
    gemm_tc<128><<<dim3(16, 8, 16), 256, SMB128, s1>>>(
        qrh, qrl, krah, kral, out + OUT_SCORES + 8L * 1024 * 2048, nullptr, nullptr, nullptr,
        128, 1024, 1024, 2048,
        8, 1024L * 1024, 128L, 2048L * 1024, 128L,
        16L * 1024 * 2048, 1024L * 2048,
        0.08838834764831845f, 0);
    cudaEventRecord(eS1, s1);

    // === main: scores h0-7 (needs key_c) ===
    cudaStreamWaitEvent(0, eKeyc, 0);
    gemm_tc<128><<<dim3(16, 8, 16), 256, SMB128>>>(
        qh, ql, kch, kcl, out + OUT_SCORES, nullptr, nullptr, nullptr,
        128, 1024, 1024, 2048,
        8, 1024L * 1024, 128L, 2048L * 1024, 128L,
        16L * 1024 * 2048, 1024L * 2048,
        0.08838834764831845f, 0);

    // softmax h0-7 (main)
    softmax_kernel<<<dim3(8192, 2), 256>>>(
        out + OUT_SCORES, vlens, out + OUT_ATTN, pbh, pbl, 0);
    cudaEventRecord(eSm0, 0);

    // === s1: AV h0-7 then out1 (K-cols 0-511) ===
    cudaStreamWaitEvent(s1, eSm0, 0);
    gemm_tc<64><<<dim3(1, 8, 16), 256, SMB64, s1>>>(
        pbh, pbl, vth, vtl, nullptr, nullptr, hoh, hol,
        2048, 2048, 2048, 1024,
        8, 16L * 1024 * 2048, 1024L * 2048,
        1024L * 2048, 64L * 2048,
        1024L * 1024, 64L,
        1.f, 0);
    // out1 = head_out[:, 0:512] @ W_o[0:512, :]   (heads 0-7)
    gemm_tc<64><<<dim3(32, 16, 1), 256, SMB64, s1>>>(
        hoh, hol, WoTh, WoTl, out + OUT_OUT, nullptr, nullptr, nullptr,
        512, 1024, 1024, 2048, 1, 0, 0, 0, 0, 0, 0, 1.f, 0);
    cudaEventRecord(eOut1, s1);

    // === main: softmax h8-15, AV h8-15, then out2 (accumulate) ===
    cudaStreamWaitEvent(0, eS1, 0);
    softmax_kernel<<<dim3(8192, 2), 256>>>(
        out + OUT_SCORES, vlens, out + OUT_ATTN, pbh, pbl, 8);
    cudaStreamWaitEvent(0, eVal, 0);
    gemm_tc<64><<<dim3(1, 8, 16), 256, SMB64>>>(
        pbh + 8L * 1024 * 2048, pbl + 8L * 1024 * 2048,
        vth + 8L * 64 * 2048, vtl + 8L * 64 * 2048,
        nullptr, nullptr, hoh + 8L * 64, hol + 8L * 64,
        2048, 2048, 2048, 1024,
        8, 16L * 1024 * 2048, 1024L * 2048,
        1024L * 2048, 64L * 2048,
        1024L * 1024, 64L,
        1.f, 0);

    // out2 += head_out[:, 512:1024] @ W_o[512:1024, :]   (heads 8-15)
    cudaStreamWaitEvent(0, eOut1, 0);
    gemm_tc<64><<<dim3(32, 16, 1), 256, SMB64>>>(
        hoh + 512, hol + 512, WoTh + 512, WoTl + 512, out + OUT_OUT,
        nullptr, nullptr, nullptr,
        512, 1024, 1024, 2048, 1, 0, 0, 0, 0, 0, 0, 1.f, 1);
}

// round 16
// speedup vs baseline: 1.0305x; 1.0305x over previous
#include <cuda_runtime.h>
#include <cuda_bf16.h>
#include <cstdint>

typedef __nv_bfloat16 bf16;

// Output layout (floats): out, z_all, key_rope_all, attn_weights, scores
#define OUT_OUT    0L
#define OUT_ZALL   4194304L
#define OUT_KRA    8388608L
#define OUT_ATTN   12582912L
#define OUT_SCORES 79691776L

// ---------------------------------------------------------------------------
// Scratch
// ---------------------------------------------------------------------------
__device__ float g_qx    [2048L*1024];
__device__ float g_kx    [2048L*1024];

__device__ bf16 g_xh[2048L*2048], g_xl[2048L*2048];
__device__ bf16 g_zallh[4096L*1024], g_zalll[4096L*1024];
__device__ bf16 g_qlath[2048L*1024], g_qlatl[2048L*1024];
__device__ bf16 g_qh [2048L*1024], g_ql [2048L*1024];
__device__ bf16 g_qrh[2048L*1024], g_qrl[2048L*1024];
__device__ bf16 g_kch[4096L*1024], g_kcl[4096L*1024];
__device__ bf16 g_krah[4096L*1024], g_kral[4096L*1024];
__device__ bf16 g_vth[2L*1024*2048], g_vtl[2L*1024*2048];
__device__ bf16 g_hoh[2048L*1024], g_hol[2048L*1024];
__device__ bf16 g_pbh[67108864L], g_pbl[67108864L];

__device__ bf16 g_WlatTh[2097152], g_WlatTl[2097152];
__device__ bf16 g_WqdTh [2097152], g_WqdTl [2097152];
__device__ bf16 g_WquTh [1048576], g_WquTl [1048576];
__device__ bf16 g_WxrTh [1048576], g_WxrTl [1048576];
__device__ bf16 g_WkuTh [1048576], g_WkuTl [1048576];
__device__ bf16 g_WvuTh [1048576], g_WvuTl [1048576];
__device__ bf16 g_WkrTh [2097152], g_WkrTl [2097152];
__device__ bf16 g_WoTh  [2097152], g_WoTl  [2097152];

// ---------------------------------------------------------------------------
// Helpers
// ---------------------------------------------------------------------------
__device__ __forceinline__ uint32_t smem_u32(const void* p) {
    uint32_t a;
    asm("{ .reg .u64 t; cvta.to.shared.u64 t, %1; cvt.u32.u64 %0, t; }" : "=r"(a) : "l"(p));
    return a;
}
#define SW128X(o) ((o) ^ (((o) >> 3) & 0x70))

__device__ __forceinline__ void ldm4(uint32_t* r, uint32_t addr) {
    asm volatile("ldmatrix.sync.aligned.m8n8.x4.shared.b16 {%0,%1,%2,%3}, [%4];"
        : "=r"(r[0]), "=r"(r[1]), "=r"(r[2]), "=r"(r[3]) : "r"(addr));
}
__device__ __forceinline__ void mma_bf16(float* c, const uint32_t* a, const uint32_t* b) {
    asm volatile("mma.sync.aligned.m16n8k16.row.col.f32.bf16.bf16.f32 "
        "{%0,%1,%2,%3}, {%4,%5,%6,%7}, {%8,%9}, {%0,%1,%2,%3};"
        : "+f"(c[0]), "+f"(c[1]), "+f"(c[2]), "+f"(c[3])
        : "r"(a[0]), "r"(a[1]), "r"(a[2]), "r"(a[3]), "r"(b[0]), "r"(b[1]));
}
__device__ __forceinline__ void cp16(uint32_t dst, const void* src) {
    asm volatile("cp.async.cg.shared.global [%0], [%1], 16;" :: "r"(dst), "l"(src));
}
__device__ __forceinline__ uint32_t pack2(float a, float b) {
    bf16 ha = __float2bfloat16(a), hb = __float2bfloat16(b);
    return (uint32_t)((__nv_bfloat16_raw)ha).x | ((uint32_t)((__nv_bfloat16_raw)hb).x << 16);
}

// ---------------------------------------------------------------------------
// Split-bf16 HMMA GEMM (proven; unchanged)
// ---------------------------------------------------------------------------
template<int NT>
__global__ void __launch_bounds__(256, NT == 64 ? 2 : 1) gemm_tc(
    const bf16* __restrict__ Ah, const bf16* __restrict__ Al,
    const bf16* __restrict__ Bh, const bf16* __restrict__ Bl,
    float* C, const float* bias, bf16* Ch, bf16* Cl,
    int K, int lda, int ldb, int ldc,
    int HD, long sA1, long sA2, long sB1, long sB2, long sC1, long sC2,
    float alpha)
{
    constexpr int MI   = (NT == 128) ? 4 : 2;
    constexpr int NB   = NT / 32;
    constexpr int ABY  = 128 * 128;
    constexpr int BBY  = NT * 128;
    constexpr int BUFB = 2 * ABY + 2 * BBY;

    extern __shared__ char smem[];
    uint32_t base = (smem_u32(smem) + 1023u) & ~1023u;

    int tid = threadIdx.x;
    int lane = tid & 31, wid = tid >> 5;

    int wm = (NT == 128) ? (wid & 1) * 64 : (wid & 3) * 32;
    int wn = (NT == 128) ? (wid >> 1) * 32 : (wid >> 2) * 32;

    int z = blockIdx.z;
    int z1 = z / HD, z2 = z - z1 * HD;
    long aoff = (long)z1*sA1 + (long)z2*sA2 + (long)blockIdx.y*128*lda;
    long boff = (long)z1*sB1 + (long)z2*sB2 + (long)blockIdx.x*NT*ldb;
    const bf16 *Abh = Ah + aoff, *Abl = Al + aoff;
    const bf16 *Bbh = Bh + boff, *Bbl = Bl + boff;

    int a_r = (lane & 7) + (((lane >> 3) & 1) << 3);
    int a_c = (lane >> 4) & 1;
    int b_r = (lane & 7) + ((lane & 16) ? 8 : 0);
    int b_c = (lane >> 3) & 1;

    float acc[MI][4][4];
    #pragma unroll
    for (int i = 0; i < MI; i++)
        #pragma unroll
        for (int j = 0; j < 4; j++)
            #pragma unroll
            for (int q = 0; q < 4; q++) acc[i][j][q] = 0.f;

    int lr = tid >> 3, lc = tid & 7;
    int nch = K >> 6;

    auto load_chunk = [&](int kk, int buf) {
        uint32_t aH = base + (uint32_t)buf * BUFB;
        uint32_t aL = aH + ABY, bH = aL + ABY, bL = bH + BBY;
        #pragma unroll
        for (int it = 0; it < 4; it++) {
            int r = lr + it * 32;
            uint32_t off = SW128X((uint32_t)(r * 128 + lc * 16));
            cp16(aH + off, Abh + (long)r * lda + kk + lc * 8);
            cp16(aL + off, Abl + (long)r * lda + kk + lc * 8);
        }
        #pragma unroll
        for (int it = 0; it < NB; it++) {
            int r = lr + it * 32;
            uint32_t off = SW128X((uint32_t)(r * 128 + lc * 16));
            cp16(bH + off, Bbh + (long)r * ldb + kk + lc * 8);
            cp16(bL + off, Bbl + (long)r * ldb + kk + lc * 8);
        }
        asm volatile("cp.async.commit_group;");
    };

    load_chunk(0, 0);

    for (int c = 0; c < nch; c++) {
        if (c + 1 < nch) {
            load_chunk((c + 1) << 6, (c + 1) & 1);
            asm volatile("cp.async.wait_group 1;");
        } else {
            asm volatile("cp.async.wait_group 0;");
        }
        __syncthreads();

        uint32_t aH = base + (uint32_t)(c & 1) * BUFB;
        uint32_t aL = aH + ABY, bH = aL + ABY, bL = bH + BBY;

        #pragma unroll
        for (int ks = 0; ks < 4; ks++) {
            uint32_t afh[MI][4], afl[MI][4], bfh[8], bfl[8];
            #pragma unroll
            for (int mi = 0; mi < MI; mi++) {
                int row = wm + mi * 16 + a_r;
                uint32_t off = (uint32_t)(row * 128) + ((((ks << 1) + a_c) ^ (row & 7)) << 4);
                ldm4(afh[mi], aH + off);
                ldm4(afl[mi], aL + off);
            }
            #pragma unroll
            for (int np = 0; np < 2; np++) {
                int row = wn + np * 16 + b_r;
                uint32_t off = (uint32_t)(row * 128) + ((((ks << 1) + b_c) ^ (row & 7)) << 4);
                ldm4(&bfh[np * 4], bH + off);
                ldm4(&bfl[np * 4], bL + off);
            }
            #pragma unroll
            for (int mi = 0; mi < MI; mi++)
                #pragma unroll
                for (int ni = 0; ni < 4; ni++)
                    mma_bf16(acc[mi][ni], afh[mi], &bfh[ni * 2]);
            #pragma unroll
            for (int mi = 0; mi < MI; mi++)
                #pragma unroll
                for (int ni = 0; ni < 4; ni++)
                    mma_bf16(acc[mi][ni], afl[mi], &bfh[ni * 2]);
            #pragma unroll
            for (int mi = 0; mi < MI; mi++)
                #pragma unroll
                for (int ni = 0; ni < 4; ni++)
                    mma_bf16(acc[mi][ni], afh[mi], &bfl[ni * 2]);
        }
        __syncthreads();
    }

    long coff = (long)z1*sC1 + (long)z2*sC2
              + (long)blockIdx.y*128*ldc + (long)blockIdx.x*NT;
    int colg0 = blockIdx.x * NT;
    #pragma unroll
    for (int mi = 0; mi < MI; mi++) {
        #pragma unroll
        for (int ni = 0; ni < 4; ni++) {
            int col = wn + ni*8 + (lane & 3)*2;
            float bv0 = 0.f, bv1 = 0.f;
            if (bias) { bv0 = bias[colg0 + col]; bv1 = bias[colg0 + col + 1]; }
            int r0 = wm + mi*16 + (lane >> 2);
            float v00 = acc[mi][ni][0]*alpha + bv0, v01 = acc[mi][ni][1]*alpha + bv1;
            float v10 = acc[mi][ni][2]*alpha + bv0, v11 = acc[mi][ni][3]*alpha + bv1;
            if (C) {
                *(float2*)(C + coff + (long)r0*ldc + col)       = make_float2(v00, v01);
                *(float2*)(C + coff + (long)(r0+8)*ldc + col)   = make_float2(v10, v11);
            }
            if (Ch) {
                bf16 h00 = __float2bfloat16(v00), h01 = __float2bfloat16(v01);
                bf16 h10 = __float2bfloat16(v10), h11 = __float2bfloat16(v11);
                *(__nv_bfloat162*)(Ch + coff + (long)r0*ldc + col) = __nv_bfloat162(h00, h01);
                *(__nv_bfloat162*)(Ch + coff + (long)(r0+8)*ldc + col) = __nv_bfloat162(h10, h11);
                bf16 l00 = __float2bfloat16(v00 - __bfloat162float(h00));
                bf16 l01 = __float2bfloat16(v01 - __bfloat162float(h01));
                bf16 l10 = __float2bfloat16(v10 - __bfloat162float(h10));
                bf16 l11 = __float2bfloat16(v11 - __bfloat162float(h11));
                *(__nv_bfloat162*)(Cl + coff + (long)r0*ldc + col) = __nv_bfloat162(l00, l01);
                *(__nv_bfloat162*)(Cl + coff + (long)(r0+8)*ldc + col) = __nv_bfloat162(l10, l11);
            }
        }
    }
}

// ---------------------------------------------------------------------------
// Elementwise helpers (unchanged)
// ---------------------------------------------------------------------------
__global__ void split_kernel(const float* __restrict__ in, bf16* __restrict__ oh,
                             bf16* __restrict__ ol, long n)
{
    long i = ((long)blockIdx.x * 256 + threadIdx.x) * 4;
    if (i >= n) return;
    float4 v = *(const float4*)(in + i);
    float a[4] = {v.x, v.y, v.z, v.w};
    bf16 h0 = __float2bfloat16(a[0]), h1 = __float2bfloat16(a[1]);
    bf16 h2 = __float2bfloat16(a[2]), h3 = __float2bfloat16(a[3]);
    uint2 ho, lo;
    ho.x = pack2(a[0], a[1]); ho.y = pack2(a[2], a[3]);
    lo.x = pack2(a[0] - __bfloat162float(h0), a[1] - __bfloat162float(h1));
    lo.y = pack2(a[2] - __bfloat162float(h2), a[3] - __bfloat162float(h3));
    *(uint2*)(oh + i) = ho;
    *(uint2*)(ol + i) = lo;
}

__global__ void transpose_split(const float* __restrict__ in, bf16* __restrict__ oh,
                                bf16* __restrict__ ol, int R, int C, long sIn, long sOut)
{
    __shared__ float t[32][33];
    long ib = (long)blockIdx.z * sIn, ob = (long)blockIdx.z * sOut;
    int x = blockIdx.x * 32 + threadIdx.x;
    int y0 = blockIdx.y * 32;
    #pragma unroll
    for (int j = threadIdx.y; j < 32; j += 8)
        t[j][threadIdx.x] = in[ib + (long)(y0 + j) * C + x];
    __syncthreads();
    int ox = blockIdx.y * 32 + threadIdx.x;
    int oy0 = blockIdx.x * 32;
    #pragma unroll
    for (int j = threadIdx.y; j < 32; j += 8) {
        float v = t[threadIdx.x][j];
        bf16 h = __float2bfloat16(v);
        long o = ob + (long)(oy0 + j) * R + ox;
        oh[o] = h;
        ol[o] = __float2bfloat16(v - __bfloat162float(h));
    }
}

__global__ void copy_concat_split(const float* __restrict__ src, float* __restrict__ dst,
                                  bf16* __restrict__ oh, bf16* __restrict__ ol)
{
    long u = (long)blockIdx.x * 256 + threadIdx.x;
    if (u >= 524288L) return;
    long i = u * 4;
    long r = i >> 10, c = i & 1023;
    long b = r >> 10, l = r & 1023;
    long o = ((b * 2048) + l) * 1024 + c;
    float4 v = *(const float4*)(src + i);
    *(float4*)(dst + o) = v;
    float a[4] = {v.x, v.y, v.z, v.w};
    bf16 h0 = __float2bfloat16(a[0]), h1 = __float2bfloat16(a[1]);
    bf16 h2 = __float2bfloat16(a[2]), h3 = __float2bfloat16(a[3]);
    uint2 ho, lo;
    ho.x = pack2(a[0], a[1]); ho.y = pack2(a[2], a[3]);
    lo.x = pack2(a[0] - __bfloat162float(h0), a[1] - __bfloat162float(h1));
    lo.y = pack2(a[2] - __bfloat162float(h2), a[3] - __bfloat162float(h3));
    *(uint2*)(oh + o) = ho;
    *(uint2*)(ol + o) = lo;
}

__global__ void rotary_kernel(const float* __restrict__ src,
                              float* __restrict__ fdst,
                              bf16* __restrict__ oh, bf16* __restrict__ ol, int mode)
{
    int idx = blockIdx.x * 256 + threadIdx.x;
    if (idx >= 2048 * 16 * 32) return;
    int i = idx & 31;
    int h = (idx >> 5) & 15;
    int r = idx >> 9;
    int pos = r & 1023;
    float fr = __expf(-9.2103403719761836f * (float)i / 32.0f);
    float ang = (float)pos * fr;
    float sn, cs;
    sincosf(ang, &sn, &cs);
    const float* s = src + (long)r * 1024 + h * 64 + i;
    float s1 = s[0], s2 = s[32];
    float o1 = s1 * cs - s2 * sn;
    float o2 = s1 * sn + s2 * cs;
    long drow = mode ? ((long)(r >> 10) * 2048 + 1024 + (r & 1023)) : (long)r;
    long off = drow * 1024 + h * 64 + i;
    if (fdst) { fdst[off] = o1; fdst[off + 32] = o2; }
    bf16 h1 = __float2bfloat16(o1), h2 = __float2bfloat16(o2);
    oh[off]      = h1;
    oh[off + 32] = h2;
    ol[off]      = __float2bfloat16(o1 - __bfloat162float(h1));
    ol[off + 32] = __float2bfloat16(o2 - __bfloat162float(h2));
}

// Dual softmax, single-exp, vectorized; head-half variant.
__global__ void __launch_bounds__(256) softmax_kernel(
    const float* __restrict__ scores, const int* __restrict__ vlens,
    float* __restrict__ attn, bf16* __restrict__ ph_out, bf16* __restrict__ pl_out,
    int hOff)
{
    int b = blockIdx.y;
    long row = (long)b * 16384 + hOff * 1024 + blockIdx.x;
    int l = blockIdx.x & 1023;
    int vl = vlens[b * 1024 + l];
    const float* s = scores + row * 2048;
    int tid = threadIdx.x;
    int k0 = tid * 8;

    float4 v0 = *(const float4*)(s + k0);
    float4 v1 = *(const float4*)(s + k0 + 4);
    float va[8] = {v0.x, v0.y, v0.z, v0.w, v1.x, v1.y, v1.z, v1.w};

    float mu = -1e30f;
    #pragma unroll
    for (int i = 0; i < 8; i++) mu = fmaxf(mu, va[i]);
    __shared__ float red[16];
    #pragma unroll
    for (int o = 16; o > 0; o >>= 1)
        mu = fmaxf(mu, __shfl_xor_sync(0xffffffffu, mu, o));
    int w = tid >> 5, lane = tid & 31;
    if (lane == 0) red[w] = mu;
    __syncthreads();
    mu = -1e30f;
    #pragma unroll
    for (int i = 0; i < 8; i++) mu = fmaxf(mu, red[i]);
    __syncthreads();

    float su = 0.f, sm = 0.f;
    #pragma unroll
    for (int i = 0; i < 8; i++) {
        float e = __expf(va[i] - mu);
        va[i] = e;
        su += e;
        if (k0 + i < vl) sm += e;
    }
    #pragma unroll
    for (int o = 16; o > 0; o >>= 1) {
        su += __shfl_xor_sync(0xffffffffu, su, o);
        sm += __shfl_xor_sync(0xffffffffu, sm, o);
    }
    if (lane == 0) { red[w] = su; red[w + 8] = sm; }
    __syncthreads();
    su = 0.f; sm = 0.f;
    #pragma unroll
    for (int i = 0; i < 8; i++) { su += red[i]; sm += red[8 + i]; }
    float iu = 1.f / su, im = 1.f / sm;

    float* arow = attn + row * 2048;
    float4 a0, a1;
    a0.x = va[0]*iu; a0.y = va[1]*iu; a0.z = va[2]*iu; a0.w = va[3]*iu;
    a1.x = va[4]*iu; a1.y = va[5]*iu; a1.z = va[6]*iu; a1.w = va[7]*iu;
    *(float4*)(arow + k0)     = a0;
    *(float4*)(arow + k0 + 4) = a1;

    float p[8];
    #pragma unroll
    for (int i = 0; i < 8; i++) p[i] = (k0 + i < vl) ? va[i] * im : 0.f;
    uint4 ho, lo;
    bf16 hb[8];
    #pragma unroll
    for (int i = 0; i < 8; i++) hb[i] = __float2bfloat16(p[i]);
    ho.x = pack2(p[0], p[1]); ho.y = pack2(p[2], p[3]);
    ho.z = pack2(p[4], p[5]); ho.w = pack2(p[6], p[7]);
    lo.x = pack2(p[0] - __bfloat162float(hb[0]), p[1] - __bfloat162float(hb[1]));
    lo.y = pack2(p[2] - __bfloat162float(hb[2]), p[3] - __bfloat162float(hb[3]));
    lo.z = pack2(p[4] - __bfloat162float(hb[4]), p[5] - __bfloat162float(hb[5]));
    lo.w = pack2(p[6] - __bfloat162float(hb[6]), p[7] - __bfloat162float(hb[7]));
    *(uint4*)(ph_out + row * 2048 + k0) = ho;
    *(uint4*)(pl_out + row * 2048 + k0) = lo;
}

// ---------------------------------------------------------------------------
// Host launch — round-14 schedule (best known): rebalanced dual chains
// + split AV tail, single K=1024 output GEMM.
// ---------------------------------------------------------------------------
#define GSYM(p, s) cudaGetSymbolAddress((void**)&(p), s)

extern "C" void kernel_launch(void* const* d_in, const int* in_sizes, int n_in,
                              void* d_out, int out_size)
{
    const float* x        = (const float*)d_in[0];
    const float* z        = (const float*)d_in[1];
    const float* key_rope = (const float*)d_in[2];
    const int*   vlens    = (const int*)  d_in[3];
    const float* W_latent = (const float*)d_in[4];
    const float* W_q_down = (const float*)d_in[5];
    const float* b_q_down = (const float*)d_in[6];
    const float* W_q_up   = (const float*)d_in[7];
    const float* W_k_up   = (const float*)d_in[8];
    const float* W_v_up   = (const float*)d_in[9];
    const float* W_x_rope = (const float*)d_in[10];
    const float* W_k_rope = (const float*)d_in[11];
    const float* W_o      = (const float*)d_in[12];
    float* out = (float*)d_out;

    float *p_qx, *p_kx;
    bf16 *xh, *xl, *zh, *zl, *qlh, *qll, *qh, *ql, *qrh, *qrl,
         *kch, *kcl, *krah, *kral, *vth, *vtl, *hoh, *hol, *pbh, *pbl;
    bf16 *WlatTh, *WlatTl, *WqdTh, *WqdTl, *WquTh, *WquTl, *WxrTh, *WxrTl,
         *WkuTh, *WkuTl, *WvuTh, *WvuTl, *WkrTh, *WkrTl, *WoTh, *WoTl;

    GSYM(p_qx, g_qx); GSYM(p_kx, g_kx);
    GSYM(xh, g_xh); GSYM(xl, g_xl); GSYM(zh, g_zallh); GSYM(zl, g_zalll);
    GSYM(qlh, g_qlath); GSYM(qll, g_qlatl);
    GSYM(qh, g_qh); GSYM(ql, g_ql); GSYM(qrh, g_qrh); GSYM(qrl, g_qrl);
    GSYM(kch, g_kch); GSYM(kcl, g_kcl); GSYM(krah, g_krah); GSYM(kral, g_kral);
    GSYM(vth, g_vth); GSYM(vtl, g_vtl); GSYM(hoh, g_hoh); GSYM(hol, g_hol);
    GSYM(pbh, g_pbh); GSYM(pbl, g_pbl);
    GSYM(WlatTh, g_WlatTh); GSYM(WlatTl, g_WlatTl);
    GSYM(WqdTh, g_WqdTh);   GSYM(WqdTl, g_WqdTl);
    GSYM(WquTh, g_WquTh);   GSYM(WquTl, g_WquTl);
    GSYM(WxrTh, g_WxrTh);   GSYM(WxrTl, g_WxrTl);
    GSYM(WkuTh, g_WkuTh);   GSYM(WkuTl, g_WkuTl);
    GSYM(WvuTh, g_WvuTh);   GSYM(WvuTl, g_WvuTl);
    GSYM(WkrTh, g_WkrTh);   GSYM(WkrTl, g_WkrTl);
    GSYM(WoTh, g_WoTh);     GSYM(WoTl, g_WoTl);

    const int SMB64  = 99328;
    const int SMB128 = 132096;
    cudaFuncSetAttribute(gemm_tc<64>,  cudaFuncAttributeMaxDynamicSharedMemorySize, SMB64);
    cudaFuncSetAttribute(gemm_tc<128>, cudaFuncAttributeMaxDynamicSharedMemorySize, SMB128);
    dim3 tb(32, 8);

    static cudaStream_t s1 = nullptr;
    static cudaEvent_t eStart = nullptr, eX = nullptr, eKeyc = nullptr,
                       eRotQ = nullptr, eS1 = nullptr, eVal = nullptr,
                       eSm0 = nullptr, eAV0 = nullptr;
    if (!s1) {
        cudaStreamCreateWithFlags(&s1, cudaStreamNonBlocking);
        cudaEventCreateWithFlags(&eStart, cudaEventDisableTiming);
        cudaEventCreateWithFlags(&eX,     cudaEventDisableTiming);
        cudaEventCreateWithFlags(&eKeyc,  cudaEventDisableTiming);
        cudaEventCreateWithFlags(&eRotQ,  cudaEventDisableTiming);
        cudaEventCreateWithFlags(&eS1,    cudaEventDisableTiming);
        cudaEventCreateWithFlags(&eVal,   cudaEventDisableTiming);
        cudaEventCreateWithFlags(&eSm0,   cudaEventDisableTiming);
        cudaEventCreateWithFlags(&eAV0,   cudaEventDisableTiming);
    }

    // === fork at t=0 ===
    cudaEventRecord(eStart, 0);
    cudaStreamWaitEvent(s1, eStart, 0);

    // === chain B (s1): transposes + z copy (overlap x split), then z path ===
    transpose_split<<<dim3(32, 64, 1), tb, 0, s1>>>(W_latent, WlatTh, WlatTl, 2048, 1024, 0, 0);
    transpose_split<<<dim3(32, 32, 1), tb, 0, s1>>>(W_k_up,   WkuTh,  WkuTl,  1024, 1024, 0, 0);
    transpose_split<<<dim3(32, 32, 1), tb, 0, s1>>>(W_v_up,   WvuTh,  WvuTl,  1024, 1024, 0, 0);
    transpose_split<<<dim3(32, 64, 1), tb, 0, s1>>>(W_k_rope, WkrTh,  WkrTl,  2048, 1024, 0, 0);
    copy_concat_split<<<2048, 256, 0, s1>>>(z, out + OUT_ZALL, zh, zl);

    // === chain A (main): x split + q-path weights ===
    split_kernel<<<4096, 256>>>(x, xh, xl, 4194304L);
    cudaEventRecord(eX, 0);
    transpose_split<<<dim3(32, 64, 1), tb>>>(W_q_down, WqdTh, WqdTl, 2048, 1024, 0, 0);
    transpose_split<<<dim3(32, 32, 1), tb>>>(W_q_up,   WquTh, WquTl, 1024, 1024, 0, 0);
    transpose_split<<<dim3(32, 32, 1), tb>>>(W_x_rope, WxrTh, WxrTl, 1024, 1024, 0, 0);
    transpose_split<<<dim3(64, 32, 1), tb>>>(W_o,      WoTh,  WoTl,  1024, 2048, 0, 0);
    copy_concat_split<<<2048, 256>>>(key_rope, out + OUT_KRA, krah, kral);

    // === chain B GEMMs: z_all -> key_c -> vt -> kx -> rotary-k ===
    cudaStreamWaitEvent(s1, eX, 0);
    gemm_tc<64><<<dim3(16, 8, 2), 256, SMB64, s1>>>(
        xh, xl, WlatTh, WlatTl, out + OUT_ZALL + 1024L * 1024, nullptr,
        zh + 1024L * 1024, zl + 1024L * 1024,
        2048, 2048, 2048, 1024,
        1, 1024L * 2048, 0, 0, 0, 2048L * 1024, 0, 1.f);
    gemm_tc<64><<<dim3(16, 32, 1), 256, SMB64, s1>>>(
        zh, zl, WkuTh, WkuTl, nullptr, nullptr, kch, kcl,
        1024, 1024, 1024, 1024, 1, 0, 0, 0, 0, 0, 0, 1.f);
    cudaEventRecord(eKeyc, s1);
    // vt[b] = W_v_up^T(split) @ z_all[b]^T
    gemm_tc<64><<<dim3(32, 8, 2), 256, SMB64, s1>>>(
        WvuTh, WvuTl, zh, zl, nullptr, nullptr, vth, vtl,
        1024, 1024, 1024, 2048,
        1, 0, 0, 2048L * 1024, 0, 1024L * 2048, 0, 1.f);
    cudaEventRecord(eVal, s1);
    // kx = x @ W_k_rope
    gemm_tc<64><<<dim3(16, 16, 1), 256, SMB64, s1>>>(
        xh, xl, WkrTh, WkrTl, p_kx, nullptr, nullptr, nullptr,
        2048, 2048, 2048, 1024, 1, 0, 0, 0, 0, 0, 0, 1.f);
    rotary_kernel<<<4096, 256, 0, s1>>>(p_kx, out + OUT_KRA, krah, kral, 1);

    // === chain A GEMMs: q_lat -> qx -> query -> rotary-q ===
    gemm_tc<64><<<dim3(16, 16, 1), 256, SMB64>>>(
        xh, xl, WqdTh, WqdTl, nullptr, b_q_down, qlh, qll,
        2048, 2048, 2048, 1024, 1, 0, 0, 0, 0, 0, 0, 1.f);
    gemm_tc<64><<<dim3(16, 16, 1), 256, SMB64>>>(
        qlh, qll, WxrTh, WxrTl, p_qx, nullptr, nullptr, nullptr,
        1024, 1024, 1024, 1024, 1, 0, 0, 0, 0, 0, 0, 1.f);
    gemm_tc<64><<<dim3(16, 16, 1), 256, SMB64>>>(
        qlh, qll, WquTh, WquTl, nullptr, nullptr, qh, ql,
        1024, 1024, 1024, 1024, 1, 0, 0, 0, 0, 0, 0, 1.f);
    rotary_kernel<<<4096, 256>>>(p_qx, nullptr, qrh, qrl, 0);
    cudaEventRecord(eRotQ, 0);

    // === s1: scores h8-15 (needs rotary-q from main + rotary-k local) ===
    cudaStreamWaitEvent(s1, eRotQ, 0);
    gemm_tc<128><<<dim3(16, 8, 16), 256, SMB128, s1>>>(
        qrh, qrl, krah, kral, out + OUT_SCORES + 8L * 1024 * 2048, nullptr, nullptr, nullptr,
        128, 1024, 1024, 2048,
        8, 1024L * 1024, 128L, 2048L * 1024, 128L,
        16L * 1024 * 2048, 1024L * 2048,
        0.08838834764831845f);
    cudaEventRecord(eS1, s1);

    // === main: scores h0-7 (needs key_c) ===
    cudaStreamWaitEvent(0, eKeyc, 0);
    gemm_tc<128><<<dim3(16, 8, 16), 256, SMB128>>>(
        qh, ql, kch, kcl, out + OUT_SCORES, nullptr, nullptr, nullptr,
        128, 1024, 1024, 2048,
        8, 1024L * 1024, 128L, 2048L * 1024, 128L,
        16L * 1024 * 2048, 1024L * 2048,
        0.08838834764831845f);

    // softmax h0-7 (main)
    softmax_kernel<<<dim3(8192, 2), 256>>>(
        out + OUT_SCORES, vlens, out + OUT_ATTN, pbh, pbl, 0);
    cudaEventRecord(eSm0, 0);

    // === s1: AV h0-7 (needs probs h0-7 + vt; vt already done on s1) ===
    cudaStreamWaitEvent(s1, eSm0, 0);
    gemm_tc<64><<<dim3(1, 8, 16), 256, SMB64, s1>>>(
        pbh, pbl, vth, vtl, nullptr, nullptr, hoh, hol,
        2048, 2048, 2048, 1024,
        8, 16L * 1024 * 2048, 1024L * 2048,
        1024L * 2048, 64L * 2048,
        1024L * 1024, 64L,
        1.f);
    cudaEventRecord(eAV0, s1);

    // === main: softmax h8-15, then AV h8-15 ===
    cudaStreamWaitEvent(0, eS1, 0);
    softmax_kernel<<<dim3(8192, 2), 256>>>(
        out + OUT_SCORES, vlens, out + OUT_ATTN, pbh, pbl, 8);
    cudaStreamWaitEvent(0, eVal, 0);
    gemm_tc<64><<<dim3(1, 8, 16), 256, SMB64>>>(
        pbh + 8L * 1024 * 2048, pbl + 8L * 1024 * 2048,
        vth + 8L * 64 * 2048, vtl + 8L * 64 * 2048,
        nullptr, nullptr, hoh + 8L * 64, hol + 8L * 64,
        2048, 2048, 2048, 1024,
        8, 16L * 1024 * 2048, 1024L * 2048,
        1024L * 2048, 64L * 2048,
        1024L * 1024, 64L,
        1.f);

    // out = head_out @ W_o (needs both AV halves)
    cudaStreamWaitEvent(0, eAV0, 0);
    gemm_tc<64><<<dim3(32, 16, 1), 256, SMB64>>>(
        hoh, hol, WoTh, WoTl, out + OUT_OUT, nullptr, nullptr, nullptr,
        1024, 1024, 1024, 2048, 1, 0, 0, 0, 0, 0, 0, 1.f);
}

// round 17
// speedup vs baseline: 1.0471x; 1.0160x over previous
#include <cuda_runtime.h>
#include <cuda_bf16.h>
#include <cstdint>

typedef __nv_bfloat16 bf16;

// Output layout (floats): out, z_all, key_rope_all, attn_weights, scores
#define OUT_OUT    0L
#define OUT_ZALL   4194304L
#define OUT_KRA    8388608L
#define OUT_ATTN   12582912L
#define OUT_SCORES 79691776L

// ---------------------------------------------------------------------------
// Scratch
// ---------------------------------------------------------------------------
__device__ float g_qx    [2048L*1024];
__device__ float g_kx    [2048L*1024];

__device__ bf16 g_xh[2048L*2048], g_xl[2048L*2048];
__device__ bf16 g_zallh[4096L*1024], g_zalll[4096L*1024];
__device__ bf16 g_qlath[2048L*1024], g_qlatl[2048L*1024];
__device__ bf16 g_qh [2048L*1024], g_ql [2048L*1024];
__device__ bf16 g_qrh[2048L*1024], g_qrl[2048L*1024];
__device__ bf16 g_kch[4096L*1024], g_kcl[4096L*1024];
__device__ bf16 g_krah[4096L*1024], g_kral[4096L*1024];
__device__ bf16 g_vth[2L*1024*2048], g_vtl[2L*1024*2048];
__device__ bf16 g_hoh[2048L*1024], g_hol[2048L*1024];
__device__ bf16 g_pbh[67108864L], g_pbl[67108864L];

__device__ bf16 g_WlatTh[2097152], g_WlatTl[2097152];
__device__ bf16 g_WqdTh [2097152], g_WqdTl [2097152];
__device__ bf16 g_WquTh [1048576], g_WquTl [1048576];
__device__ bf16 g_WxrTh [1048576], g_WxrTl [1048576];
__device__ bf16 g_WkuTh [1048576], g_WkuTl [1048576];
__device__ bf16 g_WvuTh [1048576], g_WvuTl [1048576];
__device__ bf16 g_WkrTh [2097152], g_WkrTl [2097152];
__device__ bf16 g_WoTh  [2097152], g_WoTl  [2097152];

// ---------------------------------------------------------------------------
// Helpers
// ---------------------------------------------------------------------------
__device__ __forceinline__ uint32_t smem_u32(const void* p) {
    uint32_t a;
    asm("{ .reg .u64 t; cvta.to.shared.u64 t, %1; cvt.u32.u64 %0, t; }" : "=r"(a) : "l"(p));
    return a;
}
#define SW128X(o) ((o) ^ (((o) >> 3) & 0x70))

__device__ __forceinline__ void ldm4(uint32_t* r, uint32_t addr) {
    asm volatile("ldmatrix.sync.aligned.m8n8.x4.shared.b16 {%0,%1,%2,%3}, [%4];"
        : "=r"(r[0]), "=r"(r[1]), "=r"(r[2]), "=r"(r[3]) : "r"(addr));
}
__device__ __forceinline__ void mma_bf16(float* c, const uint32_t* a, const uint32_t* b) {
    asm volatile("mma.sync.aligned.m16n8k16.row.col.f32.bf16.bf16.f32 "
        "{%0,%1,%2,%3}, {%4,%5,%6,%7}, {%8,%9}, {%0,%1,%2,%3};"
        : "+f"(c[0]), "+f"(c[1]), "+f"(c[2]), "+f"(c[3])
        : "r"(a[0]), "r"(a[1]), "r"(a[2]), "r"(a[3]), "r"(b[0]), "r"(b[1]));
}
__device__ __forceinline__ void cp16(uint32_t dst, const void* src) {
    asm volatile("cp.async.cg.shared.global [%0], [%1], 16;" :: "r"(dst), "l"(src));
}
__device__ __forceinline__ uint32_t pack2(float a, float b) {
    bf16 ha = __float2bfloat16(a), hb = __float2bfloat16(b);
    return (uint32_t)((__nv_bfloat16_raw)ha).x | ((uint32_t)((__nv_bfloat16_raw)hb).x << 16);
}

// ---------------------------------------------------------------------------
// NT=64 split-bf16 HMMA GEMM, 128 threads / 4 warps.
// Each warp: 32 M-rows (MI=2) x all 64 N-cols (NI=8)  -> A frag dup 1x, B dup 4x.
// Tile 128 x 64, K-chunk 64, cp.async double buffered (96KB smem, 2 CTAs/SM).
// ---------------------------------------------------------------------------
__global__ void __launch_bounds__(128, 2) gemm_tc64(
    const bf16* __restrict__ Ah, const bf16* __restrict__ Al,
    const bf16* __restrict__ Bh, const bf16* __restrict__ Bl,
    float* C, const float* bias, bf16* Ch, bf16* Cl,
    int K, int lda, int ldb, int ldc,
    int HD, long sA1, long sA2, long sB1, long sB2, long sC1, long sC2,
    float alpha)
{
    constexpr int ABY  = 128 * 128;   // 16 KB per A tile (h or l)
    constexpr int BBY  = 64 * 128;    // 8 KB per B tile
    constexpr int BUFB = 2 * ABY + 2 * BBY;   // 48 KB per stage

    extern __shared__ char smem[];
    uint32_t base = (smem_u32(smem) + 1023u) & ~1023u;

    int tid = threadIdx.x;
    int lane = tid & 31, wid = tid >> 5;
    int wm = wid * 32;

    int z = blockIdx.z;
    int z1 = z / HD, z2 = z - z1 * HD;
    long aoff = (long)z1*sA1 + (long)z2*sA2 + (long)blockIdx.y*128*lda;
    long boff = (long)z1*sB1 + (long)z2*sB2 + (long)blockIdx.x*64*ldb;
    const bf16 *Abh = Ah + aoff, *Abl = Al + aoff;
    const bf16 *Bbh = Bh + boff, *Bbl = Bl + boff;

    int a_r = (lane & 7) + (((lane >> 3) & 1) << 3);
    int a_c = (lane >> 4) & 1;
    int b_r = (lane & 7) + ((lane & 16) ? 8 : 0);
    int b_c = (lane >> 3) & 1;

    float acc[2][8][4];
    #pragma unroll
    for (int i = 0; i < 2; i++)
        #pragma unroll
        for (int j = 0; j < 8; j++)
            #pragma unroll
            for (int q = 0; q < 4; q++) acc[i][j][q] = 0.f;

    int lr = tid >> 3, lc = tid & 7;   // lr 0..15
    int nch = K >> 6;

    auto load_chunk = [&](int kk, int buf) {
        uint32_t aH = base + (uint32_t)buf * BUFB;
        uint32_t aL = aH + ABY, bH = aL + ABY, bL = bH + BBY;
        #pragma unroll
        for (int it = 0; it < 8; it++) {          // A: 128 rows / 16 per iter
            int r = lr + it * 16;
            uint32_t off = SW128X((uint32_t)(r * 128 + lc * 16));
            cp16(aH + off, Abh + (long)r * lda + kk + lc * 8);
            cp16(aL + off, Abl + (long)r * lda + kk + lc * 8);
        }
        #pragma unroll
        for (int it = 0; it < 4; it++) {          // B: 64 rows
            int r = lr + it * 16;
            uint32_t off = SW128X((uint32_t)(r * 128 + lc * 16));
            cp16(bH + off, Bbh + (long)r * ldb + kk + lc * 8);
            cp16(bL + off, Bbl + (long)r * ldb + kk + lc * 8);
        }
        asm volatile("cp.async.commit_group;");
    };

    load_chunk(0, 0);

    for (int c = 0; c < nch; c++) {
        if (c + 1 < nch) {
            load_chunk((c + 1) << 6, (c + 1) & 1);
            asm volatile("cp.async.wait_group 1;");
        } else {
            asm volatile("cp.async.wait_group 0;");
        }
        __syncthreads();

        uint32_t aH = base + (uint32_t)(c & 1) * BUFB;
        uint32_t aL = aH + ABY, bH = aL + ABY, bL = bH + BBY;

        #pragma unroll
        for (int ks = 0; ks < 4; ks++) {
            uint32_t afh[2][4], afl[2][4], bfh[16], bfl[16];
            #pragma unroll
            for (int mi = 0; mi < 2; mi++) {
                int row = wm + mi * 16 + a_r;
                uint32_t off = (uint32_t)(row * 128) + ((((ks << 1) + a_c) ^ (row & 7)) << 4);
                ldm4(afh[mi], aH + off);
                ldm4(afl[mi], aL + off);
            }
            #pragma unroll
            for (int np = 0; np < 4; np++) {
                int row = np * 16 + b_r;
                uint32_t off = (uint32_t)(row * 128) + ((((ks << 1) + b_c) ^ (row & 7)) << 4);
                ldm4(&bfh[np * 4], bH + off);
                ldm4(&bfl[np * 4], bL + off);
            }
            #pragma unroll
            for (int mi = 0; mi < 2; mi++)
                #pragma unroll
                for (int ni = 0; ni < 8; ni++)
                    mma_bf16(acc[mi][ni], afh[mi], &bfh[ni * 2]);
            #pragma unroll
            for (int mi = 0; mi < 2; mi++)
                #pragma unroll
                for (int ni = 0; ni < 8; ni++)
                    mma_bf16(acc[mi][ni], afl[mi], &bfh[ni * 2]);
            #pragma unroll
            for (int mi = 0; mi < 2; mi++)
                #pragma unroll
                for (int ni = 0; ni < 8; ni++)
                    mma_bf16(acc[mi][ni], afh[mi], &bfl[ni * 2]);
        }
        __syncthreads();
    }

    long coff = (long)z1*sC1 + (long)z2*sC2
              + (long)blockIdx.y*128*ldc + (long)blockIdx.x*64;
    int colg0 = blockIdx.x * 64;
    #pragma unroll
    for (int mi = 0; mi < 2; mi++) {
        #pragma unroll
        for (int ni = 0; ni < 8; ni++) {
            int col = ni*8 + (lane & 3)*2;
            float bv0 = 0.f, bv1 = 0.f;
            if (bias) { bv0 = bias[colg0 + col]; bv1 = bias[colg0 + col + 1]; }
            int r0 = wm + mi*16 + (lane >> 2);
            float v00 = acc[mi][ni][0]*alpha + bv0, v01 = acc[mi][ni][1]*alpha + bv1;
            float v10 = acc[mi][ni][2]*alpha + bv0, v11 = acc[mi][ni][3]*alpha + bv1;
            if (C) {
                *(float2*)(C + coff + (long)r0*ldc + col)       = make_float2(v00, v01);
                *(float2*)(C + coff + (long)(r0+8)*ldc + col)   = make_float2(v10, v11);
            }
            if (Ch) {
                bf16 h00 = __float2bfloat16(v00), h01 = __float2bfloat16(v01);
                bf16 h10 = __float2bfloat16(v10), h11 = __float2bfloat16(v11);
                *(__nv_bfloat162*)(Ch + coff + (long)r0*ldc + col) = __nv_bfloat162(h00, h01);
                *(__nv_bfloat162*)(Ch + coff + (long)(r0+8)*ldc + col) = __nv_bfloat162(h10, h11);
                bf16 l00 = __float2bfloat16(v00 - __bfloat162float(h00));
                bf16 l01 = __float2bfloat16(v01 - __bfloat162float(h01));
                bf16 l10 = __float2bfloat16(v10 - __bfloat162float(h10));
                bf16 l11 = __float2bfloat16(v11 - __bfloat162float(h11));
                *(__nv_bfloat162*)(Cl + coff + (long)r0*ldc + col) = __nv_bfloat162(l00, l01);
                *(__nv_bfloat162*)(Cl + coff + (long)(r0+8)*ldc + col) = __nv_bfloat162(l10, l11);
            }
        }
    }
}

// ---------------------------------------------------------------------------
// NT=128 split-bf16 HMMA GEMM (proven; used for scores)
// ---------------------------------------------------------------------------
__global__ void __launch_bounds__(256, 1) gemm_tc128(
    const bf16* __restrict__ Ah, const bf16* __restrict__ Al,
    const bf16* __restrict__ Bh, const bf16* __restrict__ Bl,
    float* C, const float* bias, bf16* Ch, bf16* Cl,
    int K, int lda, int ldb, int ldc,
    int HD, long sA1, long sA2, long sB1, long sB2, long sC1, long sC2,
    float alpha)
{
    constexpr int MI   = 4;
    constexpr int NB   = 4;
    constexpr int ABY  = 128 * 128;
    constexpr int BBY  = 128 * 128;
    constexpr int BUFB = 2 * ABY + 2 * BBY;

    extern __shared__ char smem[];
    uint32_t base = (smem_u32(smem) + 1023u) & ~1023u;

    int tid = threadIdx.x;
    int lane = tid & 31, wid = tid >> 5;

    int wm = (wid & 1) * 64;
    int wn = (wid >> 1) * 32;

    int z = blockIdx.z;
    int z1 = z / HD, z2 = z - z1 * HD;
    long aoff = (long)z1*sA1 + (long)z2*sA2 + (long)blockIdx.y*128*lda;
    long boff = (long)z1*sB1 + (long)z2*sB2 + (long)blockIdx.x*128*ldb;
    const bf16 *Abh = Ah + aoff, *Abl = Al + aoff;
    const bf16 *Bbh = Bh + boff, *Bbl = Bl + boff;

    int a_r = (lane & 7) + (((lane >> 3) & 1) << 3);
    int a_c = (lane >> 4) & 1;
    int b_r = (lane & 7) + ((lane & 16) ? 8 : 0);
    int b_c = (lane >> 3) & 1;

    float acc[MI][4][4];
    #pragma unroll
    for (int i = 0; i < MI; i++)
        #pragma unroll
        for (int j = 0; j < 4; j++)
            #pragma unroll
            for (int q = 0; q < 4; q++) acc[i][j][q] = 0.f;

    int lr = tid >> 3, lc = tid & 7;
    int nch = K >> 6;

    auto load_chunk = [&](int kk, int buf) {
        uint32_t aH = base + (uint32_t)buf * BUFB;
        uint32_t aL = aH + ABY, bH = aL + ABY, bL = bH + BBY;
        #pragma unroll
        for (int it = 0; it < 4; it++) {
            int r = lr + it * 32;
            uint32_t off = SW128X((uint32_t)(r * 128 + lc * 16));
            cp16(aH + off, Abh + (long)r * lda + kk + lc * 8);
            cp16(aL + off, Abl + (long)r * lda + kk + lc * 8);
        }
        #pragma unroll
        for (int it = 0; it < NB; it++) {
            int r = lr + it * 32;
            uint32_t off = SW128X((uint32_t)(r * 128 + lc * 16));
            cp16(bH + off, Bbh + (long)r * ldb + kk + lc * 8);
            cp16(bL + off, Bbl + (long)r * ldb + kk + lc * 8);
        }
        asm volatile("cp.async.commit_group;");
    };

    load_chunk(0, 0);

    for (int c = 0; c < nch; c++) {
        if (c + 1 < nch) {
            load_chunk((c + 1) << 6, (c + 1) & 1);
            asm volatile("cp.async.wait_group 1;");
        } else {
            asm volatile("cp.async.wait_group 0;");
        }
        __syncthreads();

        uint32_t aH = base + (uint32_t)(c & 1) * BUFB;
        uint32_t aL = aH + ABY, bH = aL + ABY, bL = bH + BBY;

        #pragma unroll
        for (int ks = 0; ks < 4; ks++) {
            uint32_t afh[MI][4], afl[MI][4], bfh[8], bfl[8];
            #pragma unroll
            for (int mi = 0; mi < MI; mi++) {
                int row = wm + mi * 16 + a_r;
                uint32_t off = (uint32_t)(row * 128) + ((((ks << 1) + a_c) ^ (row & 7)) << 4);
                ldm4(afh[mi], aH + off);
                ldm4(afl[mi], aL + off);
            }
            #pragma unroll
            for (int np = 0; np < 2; np++) {
                int row = wn + np * 16 + b_r;
                uint32_t off = (uint32_t)(row * 128) + ((((ks << 1) + b_c) ^ (row & 7)) << 4);
                ldm4(&bfh[np * 4], bH + off);
                ldm4(&bfl[np * 4], bL + off);
            }
            #pragma unroll
            for (int mi = 0; mi < MI; mi++)
                #pragma unroll
                for (int ni = 0; ni < 4; ni++)
                    mma_bf16(acc[mi][ni], afh[mi], &bfh[ni * 2]);
            #pragma unroll
            for (int mi = 0; mi < MI; mi++)
                #pragma unroll
                for (int ni = 0; ni < 4; ni++)
                    mma_bf16(acc[mi][ni], afl[mi], &bfh[ni * 2]);
            #pragma unroll
            for (int mi = 0; mi < MI; mi++)
                #pragma unroll
                for (int ni = 0; ni < 4; ni++)
                    mma_bf16(acc[mi][ni], afh[mi], &bfl[ni * 2]);
        }
        __syncthreads();
    }

    long coff = (long)z1*sC1 + (long)z2*sC2
              + (long)blockIdx.y*128*ldc + (long)blockIdx.x*128;
    #pragma unroll
    for (int mi = 0; mi < MI; mi++) {
        #pragma unroll
        for (int ni = 0; ni < 4; ni++) {
            int col = wn + ni*8 + (lane & 3)*2;
            int r0 = wm + mi*16 + (lane >> 2);
            float v00 = acc[mi][ni][0]*alpha, v01 = acc[mi][ni][1]*alpha;
            float v10 = acc[mi][ni][2]*alpha, v11 = acc[mi][ni][3]*alpha;
            *(float2*)(C + coff + (long)r0*ldc + col)     = make_float2(v00, v01);
            *(float2*)(C + coff + (long)(r0+8)*ldc + col) = make_float2(v10, v11);
        }
    }
}

// ---------------------------------------------------------------------------
// Elementwise helpers (unchanged)
// ---------------------------------------------------------------------------
__global__ void split_kernel(const float* __restrict__ in, bf16* __restrict__ oh,
                             bf16* __restrict__ ol, long n)
{
    long i = ((long)blockIdx.x * 256 + threadIdx.x) * 4;
    if (i >= n) return;
    float4 v = *(const float4*)(in + i);
    float a[4] = {v.x, v.y, v.z, v.w};
    bf16 h0 = __float2bfloat16(a[0]), h1 = __float2bfloat16(a[1]);
    bf16 h2 = __float2bfloat16(a[2]), h3 = __float2bfloat16(a[3]);
    uint2 ho, lo;
    ho.x = pack2(a[0], a[1]); ho.y = pack2(a[2], a[3]);
    lo.x = pack2(a[0] - __bfloat162float(h0), a[1] - __bfloat162float(h1));
    lo.y = pack2(a[2] - __bfloat162float(h2), a[3] - __bfloat162float(h3));
    *(uint2*)(oh + i) = ho;
    *(uint2*)(ol + i) = lo;
}

__global__ void transpose_split(const float* __restrict__ in, bf16* __restrict__ oh,
                                bf16* __restrict__ ol, int R, int C, long sIn, long sOut)
{
    __shared__ float t[32][33];
    long ib = (long)blockIdx.z * sIn, ob = (long)blockIdx.z * sOut;
    int x = blockIdx.x * 32 + threadIdx.x;
    int y0 = blockIdx.y * 32;
    #pragma unroll
    for (int j = threadIdx.y; j < 32; j += 8)
        t[j][threadIdx.x] = in[ib + (long)(y0 + j) * C + x];
    __syncthreads();
    int ox = blockIdx.y * 32 + threadIdx.x;
    int oy0 = blockIdx.x * 32;
    #pragma unroll
    for (int j = threadIdx.y; j < 32; j += 8) {
        float v = t[threadIdx.x][j];
        bf16 h = __float2bfloat16(v);
        long o = ob + (long)(oy0 + j) * R + ox;
        oh[o] = h;
        ol[o] = __float2bfloat16(v - __bfloat162float(h));
    }
}

__global__ void copy_concat_split(const float* __restrict__ src, float* __restrict__ dst,
                                  bf16* __restrict__ oh, bf16* __restrict__ ol)
{
    long u = (long)blockIdx.x * 256 + threadIdx.x;
    if (u >= 524288L) return;
    long i = u * 4;
    long r = i >> 10, c = i & 1023;
    long b = r >> 10, l = r & 1023;
    long o = ((b * 2048) + l) * 1024 + c;
    float4 v = *(const float4*)(src + i);
    *(float4*)(dst + o) = v;
    float a[4] = {v.x, v.y, v.z, v.w};
    bf16 h0 = __float2bfloat16(a[0]), h1 = __float2bfloat16(a[1]);
    bf16 h2 = __float2bfloat16(a[2]), h3 = __float2bfloat16(a[3]);
    uint2 ho, lo;
    ho.x = pack2(a[0], a[1]); ho.y = pack2(a[2], a[3]);
    lo.x = pack2(a[0] - __bfloat162float(h0), a[1] - __bfloat162float(h1));
    lo.y = pack2(a[2] - __bfloat162float(h2), a[3] - __bfloat162float(h3));
    *(uint2*)(oh + o) = ho;
    *(uint2*)(ol + o) = lo;
}

__global__ void rotary_kernel(const float* __restrict__ src,
                              float* __restrict__ fdst,
                              bf16* __restrict__ oh, bf16* __restrict__ ol, int mode)
{
    int idx = blockIdx.x * 256 + threadIdx.x;
    if (idx >= 2048 * 16 * 32) return;
    int i = idx & 31;
    int h = (idx >> 5) & 15;
    int r = idx >> 9;
    int pos = r & 1023;
    float fr = __expf(-9.2103403719761836f * (float)i / 32.0f);
    float ang = (float)pos * fr;
    float sn, cs;
    sincosf(ang, &sn, &cs);
    const float* s = src + (long)r * 1024 + h * 64 + i;
    float s1 = s[0], s2 = s[32];
    float o1 = s1 * cs - s2 * sn;
    float o2 = s1 * sn + s2 * cs;
    long drow = mode ? ((long)(r >> 10) * 2048 + 1024 + (r & 1023)) : (long)r;
    long off = drow * 1024 + h * 64 + i;
    if (fdst) { fdst[off] = o1; fdst[off + 32] = o2; }
    bf16 h1 = __float2bfloat16(o1), h2 = __float2bfloat16(o2);
    oh[off]      = h1;
    oh[off + 32] = h2;
    ol[off]      = __float2bfloat16(o1 - __bfloat162float(h1));
    ol[off + 32] = __float2bfloat16(o2 - __bfloat162float(h2));
}

// Dual softmax, single-exp, vectorized; head-half variant.
__global__ void __launch_bounds__(256) softmax_kernel(
    const float* __restrict__ scores, const int* __restrict__ vlens,
    float* __restrict__ attn, bf16* __restrict__ ph_out, bf16* __restrict__ pl_out,
    int hOff)
{
    int b = blockIdx.y;
    long row = (long)b * 16384 + hOff * 1024 + blockIdx.x;
    int l = blockIdx.x & 1023;
    int vl = vlens[b * 1024 + l];
    const float* s = scores + row * 2048;
    int tid = threadIdx.x;
    int k0 = tid * 8;

    float4 v0 = *(const float4*)(s + k0);
    float4 v1 = *(const float4*)(s + k0 + 4);
    float va[8] = {v0.x, v0.y, v0.z, v0.w, v1.x, v1.y, v1.z, v1.w};

    float mu = -1e30f;
    #pragma unroll
    for (int i = 0; i < 8; i++) mu = fmaxf(mu, va[i]);
    __shared__ float red[16];
    #pragma unroll
    for (int o = 16; o > 0; o >>= 1)
        mu = fmaxf(mu, __shfl_xor_sync(0xffffffffu, mu, o));
    int w = tid >> 5, lane = tid & 31;
    if (lane == 0) red[w] = mu;
    __syncthreads();
    mu = -1e30f;
    #pragma unroll
    for (int i = 0; i < 8; i++) mu = fmaxf(mu, red[i]);
    __syncthreads();

    float su = 0.f, sm = 0.f;
    #pragma unroll
    for (int i = 0; i < 8; i++) {
        float e = __expf(va[i] - mu);
        va[i] = e;
        su += e;
        if (k0 + i < vl) sm += e;
    }
    #pragma unroll
    for (int o = 16; o > 0; o >>= 1) {
        su += __shfl_xor_sync(0xffffffffu, su, o);
        sm += __shfl_xor_sync(0xffffffffu, sm, o);
    }
    if (lane == 0) { red[w] = su; red[w + 8] = sm; }
    __syncthreads();
    su = 0.f; sm = 0.f;
    #pragma unroll
    for (int i = 0; i < 8; i++) { su += red[i]; sm += red[8 + i]; }
    float iu = 1.f / su, im = 1.f / sm;

    float* arow = attn + row * 2048;
    float4 a0, a1;
    a0.x = va[0]*iu; a0.y = va[1]*iu; a0.z = va[2]*iu; a0.w = va[3]*iu;
    a1.x = va[4]*iu; a1.y = va[5]*iu; a1.z = va[6]*iu; a1.w = va[7]*iu;
    *(float4*)(arow + k0)     = a0;
    *(float4*)(arow + k0 + 4) = a1;

    float p[8];
    #pragma unroll
    for (int i = 0; i < 8; i++) p[i] = (k0 + i < vl) ? va[i] * im : 0.f;
    uint4 ho, lo;
    bf16 hb[8];
    #pragma unroll
    for (int i = 0; i < 8; i++) hb[i] = __float2bfloat16(p[i]);
    ho.x = pack2(p[0], p[1]); ho.y = pack2(p[2], p[3]);
    ho.z = pack2(p[4], p[5]); ho.w = pack2(p[6], p[7]);
    lo.x = pack2(p[0] - __bfloat162float(hb[0]), p[1] - __bfloat162float(hb[1]));
    lo.y = pack2(p[2] - __bfloat162float(hb[2]), p[3] - __bfloat162float(hb[3]));
    lo.z = pack2(p[4] - __bfloat162float(hb[4]), p[5] - __bfloat162float(hb[5]));
    lo.w = pack2(p[6] - __bfloat162float(hb[6]), p[7] - __bfloat162float(hb[7]));
    *(uint4*)(ph_out + row * 2048 + k0) = ho;
    *(uint4*)(pl_out + row * 2048 + k0) = lo;
}

// ---------------------------------------------------------------------------
// Host launch — round-14/16 schedule with low-dup NT=64 kernel
// ---------------------------------------------------------------------------
#define GSYM(p, s) cudaGetSymbolAddress((void**)&(p), s)

extern "C" void kernel_launch(void* const* d_in, const int* in_sizes, int n_in,
                              void* d_out, int out_size)
{
    const float* x        = (const float*)d_in[0];
    const float* z        = (const float*)d_in[1];
    const float* key_rope = (const float*)d_in[2];
    const int*   vlens    = (const int*)  d_in[3];
    const float* W_latent = (const float*)d_in[4];
    const float* W_q_down = (const float*)d_in[5];
    const float* b_q_down = (const float*)d_in[6];
    const float* W_q_up   = (const float*)d_in[7];
    const float* W_k_up   = (const float*)d_in[8];
    const float* W_v_up   = (const float*)d_in[9];
    const float* W_x_rope = (const float*)d_in[10];
    const float* W_k_rope = (const float*)d_in[11];
    const float* W_o      = (const float*)d_in[12];
    float* out = (float*)d_out;

    float *p_qx, *p_kx;
    bf16 *xh, *xl, *zh, *zl, *qlh, *qll, *qh, *ql, *qrh, *qrl,
         *kch, *kcl, *krah, *kral, *vth, *vtl, *hoh, *hol, *pbh, *pbl;
    bf16 *WlatTh, *WlatTl, *WqdTh, *WqdTl, *WquTh, *WquTl, *WxrTh, *WxrTl,
         *WkuTh, *WkuTl, *WvuTh, *WvuTl, *WkrTh, *WkrTl, *WoTh, *WoTl;

    GSYM(p_qx, g_qx); GSYM(p_kx, g_kx);
    GSYM(xh, g_xh); GSYM(xl, g_xl); GSYM(zh, g_zallh); GSYM(zl, g_zalll);
    GSYM(qlh, g_qlath); GSYM(qll, g_qlatl);
    GSYM(qh, g_qh); GSYM(ql, g_ql); GSYM(qrh, g_qrh); GSYM(qrl, g_qrl);
    GSYM(kch, g_kch); GSYM(kcl, g_kcl); GSYM(krah, g_krah); GSYM(kral, g_kral);
    GSYM(vth, g_vth); GSYM(vtl, g_vtl); GSYM(hoh, g_hoh); GSYM(hol, g_hol);
    GSYM(pbh, g_pbh); GSYM(pbl, g_pbl);
    GSYM(WlatTh, g_WlatTh); GSYM(WlatTl, g_WlatTl);
    GSYM(WqdTh, g_WqdTh);   GSYM(WqdTl, g_WqdTl);
    GSYM(WquTh, g_WquTh);   GSYM(WquTl, g_WquTl);
    GSYM(WxrTh, g_WxrTh);   GSYM(WxrTl, g_WxrTl);
    GSYM(WkuTh, g_WkuTh);   GSYM(WkuTl, g_WkuTl);
    GSYM(WvuTh, g_WvuTh);   GSYM(WvuTl, g_WvuTl);
    GSYM(WkrTh, g_WkrTh);   GSYM(WkrTl, g_WkrTl);
    GSYM(WoTh, g_WoTh);     GSYM(WoTl, g_WoTl);

    const int SMB64  = 99328;
    const int SMB128 = 132096;
    cudaFuncSetAttribute(gemm_tc64,  cudaFuncAttributeMaxDynamicSharedMemorySize, SMB64);
    cudaFuncSetAttribute(gemm_tc128, cudaFuncAttributeMaxDynamicSharedMemorySize, SMB128);
    dim3 tb(32, 8);

    static cudaStream_t s1 = nullptr;
    static cudaEvent_t eStart = nullptr, eX = nullptr, eKeyc = nullptr,
                       eRotQ = nullptr, eS1 = nullptr, eVal = nullptr,
                       eSm0 = nullptr, eAV0 = nullptr;
    if (!s1) {
        cudaStreamCreateWithFlags(&s1, cudaStreamNonBlocking);
        cudaEventCreateWithFlags(&eStart, cudaEventDisableTiming);
        cudaEventCreateWithFlags(&eX,     cudaEventDisableTiming);
        cudaEventCreateWithFlags(&eKeyc,  cudaEventDisableTiming);
        cudaEventCreateWithFlags(&eRotQ,  cudaEventDisableTiming);
        cudaEventCreateWithFlags(&eS1,    cudaEventDisableTiming);
        cudaEventCreateWithFlags(&eVal,   cudaEventDisableTiming);
        cudaEventCreateWithFlags(&eSm0,   cudaEventDisableTiming);
        cudaEventCreateWithFlags(&eAV0,   cudaEventDisableTiming);
    }

    // === fork at t=0 ===
    cudaEventRecord(eStart, 0);
    cudaStreamWaitEvent(s1, eStart, 0);

    // === chain B (s1): transposes + z copy (overlap x split), then z path ===
    transpose_split<<<dim3(32, 64, 1), tb, 0, s1>>>(W_latent, WlatTh, WlatTl, 2048, 1024, 0, 0);
    transpose_split<<<dim3(32, 32, 1), tb, 0, s1>>>(W_k_up,   WkuTh,  WkuTl,  1024, 1024, 0, 0);
    transpose_split<<<dim3(32, 32, 1), tb, 0, s1>>>(W_v_up,   WvuTh,  WvuTl,  1024, 1024, 0, 0);
    transpose_split<<<dim3(32, 64, 1), tb, 0, s1>>>(W_k_rope, WkrTh,  WkrTl,  2048, 1024, 0, 0);
    copy_concat_split<<<2048, 256, 0, s1>>>(z, out + OUT_ZALL, zh, zl);

    // === chain A (main): x split + q-path weights ===
    split_kernel<<<4096, 256>>>(x, xh, xl, 4194304L);
    cudaEventRecord(eX, 0);
    transpose_split<<<dim3(32, 64, 1), tb>>>(W_q_down, WqdTh, WqdTl, 2048, 1024, 0, 0);
    transpose_split<<<dim3(32, 32, 1), tb>>>(W_q_up,   WquTh, WquTl, 1024, 1024, 0, 0);
    transpose_split<<<dim3(32, 32, 1), tb>>>(W_x_rope, WxrTh, WxrTl, 1024, 1024, 0, 0);
    transpose_split<<<dim3(64, 32, 1), tb>>>(W_o,      WoTh,  WoTl,  1024, 2048, 0, 0);
    copy_concat_split<<<2048, 256>>>(key_rope, out + OUT_KRA, krah, kral);

    // === chain B GEMMs: z_all -> key_c -> vt -> kx -> rotary-k ===
    cudaStreamWaitEvent(s1, eX, 0);
    gemm_tc64<<<dim3(16, 8, 2), 128, SMB64, s1>>>(
        xh, xl, WlatTh, WlatTl, out + OUT_ZALL + 1024L * 1024, nullptr,
        zh + 1024L * 1024, zl + 1024L * 1024,
        2048, 2048, 2048, 1024,
        1, 1024L * 2048, 0, 0, 0, 2048L * 1024, 0, 1.f);
    gemm_tc64<<<dim3(16, 32, 1), 128, SMB64, s1>>>(
        zh, zl, WkuTh, WkuTl, nullptr, nullptr, kch, kcl,
        1024, 1024, 1024, 1024, 1, 0, 0, 0, 0, 0, 0, 1.f);
    cudaEventRecord(eKeyc, s1);
    gemm_tc64<<<dim3(32, 8, 2), 128, SMB64, s1>>>(
        WvuTh, WvuTl, zh, zl, nullptr, nullptr, vth, vtl,
        1024, 1024, 1024, 2048,
        1, 0, 0, 2048L * 1024, 0, 1024L * 2048, 0, 1.f);
    cudaEventRecord(eVal, s1);
    gemm_tc64<<<dim3(16, 16, 1), 128, SMB64, s1>>>(
        xh, xl, WkrTh, WkrTl, p_kx, nullptr, nullptr, nullptr,
        2048, 2048, 2048, 1024, 1, 0, 0, 0, 0, 0, 0, 1.f);
    rotary_kernel<<<4096, 256, 0, s1>>>(p_kx, out + OUT_KRA, krah, kral, 1);

    // === chain A GEMMs: q_lat -> qx -> query -> rotary-q ===
    gemm_tc64<<<dim3(16, 16, 1), 128, SMB64>>>(
        xh, xl, WqdTh, WqdTl, nullptr, b_q_down, qlh, qll,
        2048, 2048, 2048, 1024, 1, 0, 0, 0, 0, 0, 0, 1.f);
    gemm_tc64<<<dim3(16, 16, 1), 128, SMB64>>>(
        qlh, qll, WxrTh, WxrTl, p_qx, nullptr, nullptr, nullptr,
        1024, 1024, 1024, 1024, 1, 0, 0, 0, 0, 0, 0, 1.f);
    gemm_tc64<<<dim3(16, 16, 1), 128, SMB64>>>(
        qlh, qll, WquTh, WquTl, nullptr, nullptr, qh, ql,
        1024, 1024, 1024, 1024, 1, 0, 0, 0, 0, 0, 0, 1.f);
    rotary_kernel<<<4096, 256>>>(p_qx, nullptr, qrh, qrl, 0);
    cudaEventRecord(eRotQ, 0);

    // === s1: scores h8-15 (needs rotary-q from main + rotary-k local) ===
    cudaStreamWaitEvent(s1, eRotQ, 0);
    gemm_tc128<<<dim3(16, 8, 16), 256, SMB128, s1>>>(
        qrh, qrl, krah, kral, out + OUT_SCORES + 8L * 1024 * 2048, nullptr, nullptr, nullptr,
        128, 1024, 1024, 2048,
        8, 1024L * 1024, 128L, 2048L * 1024, 128L,
        16L * 1024 * 2048, 1024L * 2048,
        0.08838834764831845f);
    cudaEventRecord(eS1, s1);

    // === main: scores h0-7 (needs key_c) ===
    cudaStreamWaitEvent(0, eKeyc, 0);
    gemm_tc128<<<dim3(16, 8, 16), 256, SMB128>>>(
        qh, ql, kch, kcl, out + OUT_SCORES, nullptr, nullptr, nullptr,
        128, 1024, 1024, 2048,
        8, 1024L * 1024, 128L, 2048L * 1024, 128L,
        16L * 1024 * 2048, 1024L * 2048,
        0.08838834764831845f);

    // softmax h0-7 (main)
    softmax_kernel<<<dim3(8192, 2), 256>>>(
        out + OUT_SCORES, vlens, out + OUT_ATTN, pbh, pbl, 0);
    cudaEventRecord(eSm0, 0);

    // === s1: AV h0-7 ===
    cudaStreamWaitEvent(s1, eSm0, 0);
    gemm_tc64<<<dim3(1, 8, 16), 128, SMB64, s1>>>(
        pbh, pbl, vth, vtl, nullptr, nullptr, hoh, hol,
        2048, 2048, 2048, 1024,
        8, 16L * 1024 * 2048, 1024L * 2048,
        1024L * 2048, 64L * 2048,
        1024L * 1024, 64L,
        1.f);
    cudaEventRecord(eAV0, s1);

    // === main: softmax h8-15, then AV h8-15 ===
    cudaStreamWaitEvent(0, eS1, 0);
    softmax_kernel<<<dim3(8192, 2), 256>>>(
        out + OUT_SCORES, vlens, out + OUT_ATTN, pbh, pbl, 8);
    cudaStreamWaitEvent(0, eVal, 0);
    gemm_tc64<<<dim3(1, 8, 16), 128, SMB64>>>(
        pbh + 8L * 1024 * 2048, pbl + 8L * 1024 * 2048,
        vth + 8L * 64 * 2048, vtl + 8L * 64 * 2048,
        nullptr, nullptr, hoh + 8L * 64, hol + 8L * 64,
        2048, 2048, 2048, 1024,
        8, 16L * 1024 * 2048, 1024L * 2048,
        1024L * 2048, 64L * 2048,
        1024L * 1024, 64L,
        1.f);

    // out = head_out @ W_o (needs both AV halves)
    cudaStreamWaitEvent(0, eAV0, 0);
    gemm_tc64<<<dim3(32, 16, 1), 128, SMB64>>>(
        hoh, hol, WoTh, WoTl, out + OUT_OUT, nullptr, nullptr, nullptr,
        1024, 1024, 1024, 2048, 1, 0, 0, 0, 0, 0, 0, 1.f);
}